// round 2
// baseline (speedup 1.0000x reference)
#include <cuda_runtime.h>
#include <cuda_bf16.h>
#include <math.h>
#include <stdint.h>

// ---------------------------------------------------------------------------
// stGCL: N=30000 nodes, E=480000 edges, IN_X=3000, IN_R=2048, NH=256, OUT=64.
// ---------------------------------------------------------------------------
#define N_NODES  30000
#define E_EDGES  480000

// Scratch (device globals: allocation-free rule)
__device__ float g_Hx[N_NODES * 256];
__device__ float g_Hr[N_NODES * 256];
__device__ float g_T0[N_NODES * 512];
__device__ float g_T1[N_NODES * 512];
__device__ float g_U [N_NODES * 512];
__device__ float g_scal[N_NODES * 4];
__device__ int   g_rowptr[N_NODES + 1];
__device__ int   g_cnt[N_NODES];
__device__ int   g_srcs[E_EDGES];

// ---------------------------------------------------------------------------
// tf32 split: x = hi + lo (both tf32-representable), error ~2^-22 * |x|
// ---------------------------------------------------------------------------
__device__ __forceinline__ void tf32split(float x, float& hi, float& lo)
{
    uint32_t h;
    asm("cvt.rna.tf32.f32 %0, %1;" : "=r"(h) : "f"(x));
    hi = __uint_as_float(h);
    float r = x - hi;
    uint32_t l;
    asm("cvt.rna.tf32.f32 %0, %1;" : "=r"(l) : "f"(r));
    lo = __uint_as_float(l);
}

#define MMA_TF32(d, a, b)                                                     \
    asm volatile(                                                             \
        "mma.sync.aligned.m16n8k8.row.col.f32.tf32.tf32.f32 "                 \
        "{%0,%1,%2,%3},{%4,%5,%6,%7},{%8,%9},{%0,%1,%2,%3};"                  \
        : "+f"((d)[0]), "+f"((d)[1]), "+f"((d)[2]), "+f"((d)[3])              \
        : "r"(__float_as_uint((a)[0])), "r"(__float_as_uint((a)[1])),         \
          "r"(__float_as_uint((a)[2])), "r"(__float_as_uint((a)[3])),         \
          "r"(__float_as_uint((b)[0])), "r"(__float_as_uint((b)[1])))

// ---------------------------------------------------------------------------
// Tensor-core GEMM (tf32x3): C[M,N] = A[M,K] * B
//   BT=false: B is [K,N] row-major;  BT=true: B is [N,K] row-major (C=A*B^T)
// Block 128x128, BK=16, 256 threads = 8 warps of 64x32 warp-tiles.
// ---------------------------------------------------------------------------
#define ASTR 20    // smem stride for A[m][k]  (conflict-free frag loads)
#define BSTR 132   // smem stride for B[k][n]  (<=2-way conflicts)

template <bool BT>
__global__ __launch_bounds__(256)
void mma_gemm(int M, int N, int K,
              const float* __restrict__ A, int lda,
              const float* __restrict__ B, int ldb,
              float* __restrict__ C, int ldc)
{
    __shared__ float Ah[128 * ASTR];
    __shared__ float Al[128 * ASTR];
    __shared__ float Bh[16 * BSTR];
    __shared__ float Bl[16 * BSTR];

    const int tid  = threadIdx.x;
    const int lane = tid & 31;
    const int wid  = tid >> 5;
    const int g    = lane >> 2;   // group id 0..7
    const int tig  = lane & 3;    // thread-in-group 0..3
    const int wm   = (wid & 1) * 64;   // warp m offset (2 rows of warps)
    const int wn   = (wid >> 1) * 32;  // warp n offset (4 cols of warps)
    const int m0   = blockIdx.y * 128;
    const int n0   = blockIdx.x * 128;

    float acc[4][4][4];
#pragma unroll
    for (int i = 0; i < 4; i++)
#pragma unroll
        for (int j = 0; j < 4; j++)
#pragma unroll
            for (int c = 0; c < 4; c++) acc[i][j][c] = 0.f;

    for (int k0 = 0; k0 < K; k0 += 16) {
        // ---- A tile: 128 x 16, global [m][k] -> smem [m][k] (stride ASTR)
#pragma unroll
        for (int i = 0; i < 2; i++) {
            int f4  = tid * 2 + i;          // 0..511
            int row = f4 >> 2;              // m 0..127
            int kq  = f4 & 3;               // float4 within row
            int gm = m0 + row, gk = k0 + kq * 4;
            float4 v = make_float4(0.f, 0.f, 0.f, 0.f);
            if (gm < M && gk < K)           // K is a multiple of 4 always
                v = *reinterpret_cast<const float4*>(A + (size_t)gm * lda + gk);
            float4 h4, l4;
            tf32split(v.x, h4.x, l4.x);
            tf32split(v.y, h4.y, l4.y);
            tf32split(v.z, h4.z, l4.z);
            tf32split(v.w, h4.w, l4.w);
            *reinterpret_cast<float4*>(&Ah[row * ASTR + kq * 4]) = h4;
            *reinterpret_cast<float4*>(&Al[row * ASTR + kq * 4]) = l4;
        }
        // ---- B tile: 16 x 128 logical [k][n] -> smem [k][n] (stride BSTR)
        if (!BT) {
#pragma unroll
            for (int i = 0; i < 2; i++) {
                int f4 = tid * 2 + i;       // 0..511
                int kr = f4 >> 5;           // k 0..15
                int nq = f4 & 31;           // float4 within n-row
                int gk = k0 + kr, gn = n0 + nq * 4;
                float4 v = make_float4(0.f, 0.f, 0.f, 0.f);
                if (gk < K && gn < N)       // N multiple of 4
                    v = *reinterpret_cast<const float4*>(B + (size_t)gk * ldb + gn);
                float4 h4, l4;
                tf32split(v.x, h4.x, l4.x);
                tf32split(v.y, h4.y, l4.y);
                tf32split(v.z, h4.z, l4.z);
                tf32split(v.w, h4.w, l4.w);
                *reinterpret_cast<float4*>(&Bh[kr * BSTR + nq * 4]) = h4;
                *reinterpret_cast<float4*>(&Bl[kr * BSTR + nq * 4]) = l4;
            }
        } else {
#pragma unroll
            for (int i = 0; i < 2; i++) {
                int f4 = tid * 2 + i;
                int nr = f4 >> 2;           // n 0..127
                int kq = f4 & 3;
                int gn = n0 + nr, gk = k0 + kq * 4;
                float4 v = make_float4(0.f, 0.f, 0.f, 0.f);
                if (gn < N && gk < K)
                    v = *reinterpret_cast<const float4*>(B + (size_t)gn * ldb + gk);
                float h4[4], l4[4];
                tf32split(v.x, h4[0], l4[0]);
                tf32split(v.y, h4[1], l4[1]);
                tf32split(v.z, h4[2], l4[2]);
                tf32split(v.w, h4[3], l4[3]);
#pragma unroll
                for (int j = 0; j < 4; j++) {
                    Bh[(kq * 4 + j) * BSTR + nr] = h4[j];
                    Bl[(kq * 4 + j) * BSTR + nr] = l4[j];
                }
            }
        }
        __syncthreads();

#pragma unroll
        for (int ks = 0; ks < 16; ks += 8) {
            float ah[4][4], al[4][4];
#pragma unroll
            for (int mf = 0; mf < 4; mf++) {
                int mb = wm + mf * 16;
                ah[mf][0] = Ah[(mb + g    ) * ASTR + ks + tig    ];
                ah[mf][1] = Ah[(mb + g + 8) * ASTR + ks + tig    ];
                ah[mf][2] = Ah[(mb + g    ) * ASTR + ks + tig + 4];
                ah[mf][3] = Ah[(mb + g + 8) * ASTR + ks + tig + 4];
                al[mf][0] = Al[(mb + g    ) * ASTR + ks + tig    ];
                al[mf][1] = Al[(mb + g + 8) * ASTR + ks + tig    ];
                al[mf][2] = Al[(mb + g    ) * ASTR + ks + tig + 4];
                al[mf][3] = Al[(mb + g + 8) * ASTR + ks + tig + 4];
            }
            float bh[4][2], bl[4][2];
#pragma unroll
            for (int nf = 0; nf < 4; nf++) {
                int nb = wn + nf * 8 + g;
                bh[nf][0] = Bh[(ks + tig    ) * BSTR + nb];
                bh[nf][1] = Bh[(ks + tig + 4) * BSTR + nb];
                bl[nf][0] = Bl[(ks + tig    ) * BSTR + nb];
                bl[nf][1] = Bl[(ks + tig + 4) * BSTR + nb];
            }
#pragma unroll
            for (int mf = 0; mf < 4; mf++)
#pragma unroll
                for (int nf = 0; nf < 4; nf++) {
                    MMA_TF32(acc[mf][nf], ah[mf], bh[nf]);  // hi*hi
                    MMA_TF32(acc[mf][nf], al[mf], bh[nf]);  // lo*hi
                    MMA_TF32(acc[mf][nf], ah[mf], bl[nf]);  // hi*lo
                }
        }
        __syncthreads();
    }

    // ---- Epilogue
#pragma unroll
    for (int mf = 0; mf < 4; mf++) {
        int gm1 = m0 + wm + mf * 16 + g;
        int gm2 = gm1 + 8;
#pragma unroll
        for (int nf = 0; nf < 4; nf++) {
            int gn = n0 + wn + nf * 8 + tig * 2;
            if (gm1 < M) {
                if (gn     < N) C[(size_t)gm1 * ldc + gn    ] = acc[mf][nf][0];
                if (gn + 1 < N) C[(size_t)gm1 * ldc + gn + 1] = acc[mf][nf][1];
            }
            if (gm2 < M) {
                if (gn     < N) C[(size_t)gm2 * ldc + gn    ] = acc[mf][nf][2];
                if (gn + 1 < N) C[(size_t)gm2 * ldc + gn + 1] = acc[mf][nf][3];
            }
        }
    }
}

// ---------------------------------------------------------------------------
// CSR build
// ---------------------------------------------------------------------------
__global__ void hist_kernel(const int* __restrict__ dst, int* cnt, int E)
{
    int i = blockIdx.x * blockDim.x + threadIdx.x;
    if (i < E) atomicAdd(&cnt[dst[i]], 1);
}

__global__ void scan_kernel(const int* counts, int* rowptr, int* cursor, int N, int E)
{
    __shared__ int sm[1024];
    int tid = threadIdx.x;
    int ch  = (N + 1023) / 1024;
    int b   = tid * ch;
    int e   = min(b + ch, N);
    int s = 0;
    for (int i = b; i < e; i++) s += counts[i];
    sm[tid] = s;
    __syncthreads();
    for (int off = 1; off < 1024; off <<= 1) {
        int t = (tid >= off) ? sm[tid - off] : 0;
        __syncthreads();
        sm[tid] += t;
        __syncthreads();
    }
    int run = (tid == 0) ? 0 : sm[tid - 1];
    for (int i = b; i < e; i++) {
        int c = counts[i];
        rowptr[i] = run;
        cursor[i] = run;
        run += c;
    }
    if (tid == 0) rowptr[N] = E;
}

__global__ void fill_kernel(const int* __restrict__ src, const int* __restrict__ dst,
                            int* cursor, int* __restrict__ srcs, int E)
{
    int i = blockIdx.x * blockDim.x + threadIdx.x;
    if (i < E) {
        int p = atomicAdd(&cursor[dst[i]], 1);
        srcs[p] = src[i];
    }
}

// ---------------------------------------------------------------------------
// Per-node attention scalars
// ---------------------------------------------------------------------------
template <int NH>
__global__ void dots_kernel(const float* __restrict__ H,
                            const float* __restrict__ a_src,
                            const float* __restrict__ a_dst,
                            float* __restrict__ es, float* __restrict__ ed, int N)
{
    int gw   = (blockIdx.x * blockDim.x + threadIdx.x) >> 5;
    int lane = threadIdx.x & 31;
    if (gw >= N) return;
    const float* h = H + (size_t)gw * NH;
    float ps = 0.f, pd = 0.f;
#pragma unroll
    for (int c = lane; c < NH; c += 32) {
        float v = h[c];
        ps += v * __ldg(&a_src[c]);
        pd += v * __ldg(&a_dst[c]);
    }
#pragma unroll
    for (int o = 16; o; o >>= 1) {
        ps += __shfl_xor_sync(0xffffffffu, ps, o);
        pd += __shfl_xor_sync(0xffffffffu, pd, o);
    }
    if (lane == 0) { es[gw] = ps; ed[gw] = pd; }
}

// ---------------------------------------------------------------------------
// Fused GAT aggregation (segment softmax + weighted gather + elu)
// ---------------------------------------------------------------------------
template <int NH>
__global__ void gat_agg_kernel(const float* __restrict__ H,
                               const float* __restrict__ es,
                               const float* __restrict__ ed,
                               const int* __restrict__ rowptr,
                               const int* __restrict__ srcs,
                               const int* __restrict__ perm,
                               float* __restrict__ out, int out_ld, int out_off, int N)
{
    constexpr int R4 = NH / 128;
    int gw   = (blockIdx.x * blockDim.x + threadIdx.x) >> 5;
    int lane = threadIdx.x & 31;
    if (gw >= N) return;

    int beg = rowptr[gw], end = rowptr[gw + 1];
    int dsti = perm ? __ldg(&perm[gw]) : gw;
    float edd = __ldg(&ed[dsti]);

    float m = -INFINITY;
    for (int j = beg + lane; j < end; j += 32) {
        int s  = __ldg(&srcs[j]);
        int si = perm ? __ldg(&perm[s]) : s;
        float e = __ldg(&es[si]) + edd;
        e = e > 0.f ? e : 0.2f * e;
        m = fmaxf(m, e);
    }
#pragma unroll
    for (int o = 16; o; o >>= 1) m = fmaxf(m, __shfl_xor_sync(0xffffffffu, m, o));
    if (!isfinite(m)) m = 0.f;

    float4 acc[R4];
#pragma unroll
    for (int c = 0; c < R4; c++) acc[c] = make_float4(0.f, 0.f, 0.f, 0.f);
    float sumw = 0.f;

    for (int j = beg; j < end; ++j) {
        int s  = __ldg(&srcs[j]);
        int si = perm ? __ldg(&perm[s]) : s;
        float e = __ldg(&es[si]) + edd;
        e = e > 0.f ? e : 0.2f * e;
        float w = expf(e - m);
        sumw += w;
        const float4* h4 = reinterpret_cast<const float4*>(H + (size_t)si * NH) + lane;
#pragma unroll
        for (int c = 0; c < R4; c++) {
            float4 v = __ldg(&h4[c * 32]);
            acc[c].x += w * v.x; acc[c].y += w * v.y;
            acc[c].z += w * v.z; acc[c].w += w * v.w;
        }
    }

    float inv = 1.f / (sumw + 1e-16f);
    float4* o4 = reinterpret_cast<float4*>(out + (size_t)gw * out_ld + out_off) + lane;
#pragma unroll
    for (int c = 0; c < R4; c++) {
        float4 v;
        v.x = acc[c].x * inv; v.y = acc[c].y * inv;
        v.z = acc[c].z * inv; v.w = acc[c].w * inv;
        v.x = v.x > 0.f ? v.x : expm1f(v.x);
        v.y = v.y > 0.f ? v.y : expm1f(v.y);
        v.z = v.z > 0.f ? v.z : expm1f(v.z);
        v.w = v.w > 0.f ? v.w : expm1f(v.w);
        o4[c * 32] = v;
    }
}

// ---------------------------------------------------------------------------
// summary = sigmoid(mean(h2, axis=0))
// ---------------------------------------------------------------------------
__global__ void summary_kernel(const float* __restrict__ h2, float* __restrict__ out,
                               int N, int C)
{
    int c   = blockIdx.x;
    int tid = threadIdx.x;
    float s = 0.f;
    for (int r = tid; r < N; r += blockDim.x) s += h2[(size_t)r * C + c];
    __shared__ float sm[256];
    sm[tid] = s;
    __syncthreads();
    for (int o = 128; o; o >>= 1) {
        if (tid < o) sm[tid] += sm[tid + o];
        __syncthreads();
    }
    if (tid == 0) {
        float mval = sm[0] / (float)N;
        out[c] = 1.f / (1.f + expf(-mval));
    }
}

// ---------------------------------------------------------------------------
// Host orchestration
// ---------------------------------------------------------------------------
extern "C" void kernel_launch(void* const* d_in, const int* in_sizes, int n_in,
                              void* d_out, int out_size)
{
    const float* features    = (const float*)d_in[0];
    const float* im_features = (const float*)d_in[1];
    const float* W1x     = (const float*)d_in[2];
    const float* a1x_src = (const float*)d_in[3];
    const float* a1x_dst = (const float*)d_in[4];
    const float* W1r     = (const float*)d_in[5];
    const float* a1r_src = (const float*)d_in[6];
    const float* a1r_dst = (const float*)d_in[7];
    const float* W2      = (const float*)d_in[8];
    const float* a3_src  = (const float*)d_in[9];
    const float* a3_dst  = (const float*)d_in[10];
    const int*   ei      = (const int*)d_in[11];
    const int*   perm    = (const int*)d_in[12];

    const int N   = in_sizes[12];
    const int E   = in_sizes[11] / 2;
    const int NH  = in_sizes[3];
    const int INX = in_sizes[0] / N;
    const int INR = in_sizes[1] / N;
    const int OUT = in_sizes[8] / (2 * NH);

    const int* srcI = ei;
    const int* dstI = ei + E;

    float *Hx, *Hr, *T0, *T1, *U, *scal;
    int *rp, *cnt, *sr;
    cudaGetSymbolAddress((void**)&Hx,  g_Hx);
    cudaGetSymbolAddress((void**)&Hr,  g_Hr);
    cudaGetSymbolAddress((void**)&T0,  g_T0);
    cudaGetSymbolAddress((void**)&T1,  g_T1);
    cudaGetSymbolAddress((void**)&U,   g_U);
    cudaGetSymbolAddress((void**)&scal,g_scal);
    cudaGetSymbolAddress((void**)&rp,  g_rowptr);
    cudaGetSymbolAddress((void**)&cnt, g_cnt);
    cudaGetSymbolAddress((void**)&sr,  g_srcs);

    float* out = (float*)d_out;
    size_t oH2   = 0;
    size_t oH4X  = oH2   + (size_t)N * OUT;
    size_t oH4R  = oH4X  + (size_t)N * INX;
    size_t oRH2  = oH4R  + (size_t)N * INR;
    size_t oRH4X = oRH2  + (size_t)N * OUT;
    size_t oRH4R = oRH4X + (size_t)N * INX;
    size_t oSUM  = oRH4R + (size_t)N * INR;

    auto gg = [](int M, int Nn) { return dim3((unsigned)((Nn + 127) / 128),
                                              (unsigned)((M + 127) / 128)); };
    const int WGRID = (N * 32 + 255) / 256;

    // --- CSR by dst ---
    cudaMemsetAsync(cnt, 0, N * sizeof(int));
    hist_kernel<<<(E + 255) / 256, 256>>>(dstI, cnt, E);
    scan_kernel<<<1, 1024>>>(cnt, rp, cnt, N, E);
    fill_kernel<<<(E + 255) / 256, 256>>>(srcI, dstI, cnt, sr, E);

    // --- Forward projections (shared by orig & perm paths) ---
    mma_gemm<false><<<gg(N, NH), 256>>>(N, NH, INX, features,    INX, W1x, NH, Hx, NH);
    mma_gemm<false><<<gg(N, NH), 256>>>(N, NH, INR, im_features, INR, W1r, NH, Hr, NH);

    // --- Attention scalars ---
    dots_kernel<256><<<WGRID, 256>>>(Hx, a1x_src, a1x_dst, scal + 0 * N, scal + 1 * N, N);
    dots_kernel<256><<<WGRID, 256>>>(Hr, a1r_src, a1r_dst, scal + 2 * N, scal + 3 * N, N);

    // --- Encode aggregation ---
    gat_agg_kernel<256><<<WGRID, 256>>>(Hx, scal + 0 * N, scal + 1 * N, rp, sr, nullptr, T0, 512, 0,   N);
    gat_agg_kernel<256><<<WGRID, 256>>>(Hr, scal + 2 * N, scal + 3 * N, rp, sr, nullptr, T0, 512, 256, N);
    gat_agg_kernel<256><<<WGRID, 256>>>(Hx, scal + 0 * N, scal + 1 * N, rp, sr, perm,    T1, 512, 0,   N);
    gat_agg_kernel<256><<<WGRID, 256>>>(Hr, scal + 2 * N, scal + 3 * N, rp, sr, perm,    T1, 512, 256, N);

    // --- h2 = concat @ W2 ---
    mma_gemm<false><<<gg(N, OUT), 256>>>(N, OUT, 2 * NH, T0, 2 * NH, W2, OUT, out + oH2,  OUT);
    mma_gemm<false><<<gg(N, OUT), 256>>>(N, OUT, 2 * NH, T1, 2 * NH, W2, OUT, out + oRH2, OUT);

    summary_kernel<<<OUT, 256>>>(out + oH2, out + oSUM, N, OUT);

    // --- Decode: orig ---
    mma_gemm<true><<<gg(N, 2 * NH), 256>>>(N, 2 * NH, OUT, out + oH2, OUT, W2, OUT, T0, 2 * NH);
    dots_kernel<512><<<WGRID, 256>>>(T0, a3_src, a3_dst, scal + 0 * N, scal + 1 * N, N);
    gat_agg_kernel<512><<<WGRID, 256>>>(T0, scal + 0 * N, scal + 1 * N, rp, sr, nullptr, U, 512, 0, N);
    mma_gemm<true><<<gg(N, INX), 256>>>(N, INX, NH, U,       512, W1x, NH, out + oH4X, INX);
    mma_gemm<true><<<gg(N, INR), 256>>>(N, INR, NH, U + NH,  512, W1r, NH, out + oH4R, INR);

    // --- Decode: rand ---
    mma_gemm<true><<<gg(N, 2 * NH), 256>>>(N, 2 * NH, OUT, out + oRH2, OUT, W2, OUT, T1, 2 * NH);
    dots_kernel<512><<<WGRID, 256>>>(T1, a3_src, a3_dst, scal + 2 * N, scal + 3 * N, N);
    gat_agg_kernel<512><<<WGRID, 256>>>(T1, scal + 2 * N, scal + 3 * N, rp, sr, nullptr, U, 512, 0, N);
    mma_gemm<true><<<gg(N, INX), 256>>>(N, INX, NH, U,       512, W1x, NH, out + oRH4X, INX);
    mma_gemm<true><<<gg(N, INR), 256>>>(N, INR, NH, U + NH,  512, W1r, NH, out + oRH4R, INR);

    (void)n_in; (void)out_size;
}

// round 3
// speedup vs baseline: 1.4241x; 1.4241x over previous
#include <cuda_runtime.h>
#include <cuda_bf16.h>
#include <math.h>
#include <stdint.h>

// ---------------------------------------------------------------------------
// stGCL: N=30000 nodes, E=480000 edges, IN_X=3000, IN_R=2048, NH=256, OUT=64.
// ---------------------------------------------------------------------------
#define N_NODES  30000
#define E_EDGES  480000

// Scratch (device globals: allocation-free rule)
__device__ float g_Hx[N_NODES * 256];
__device__ float g_Hr[N_NODES * 256];
__device__ float g_T0[N_NODES * 512];
__device__ float g_T1[N_NODES * 512];
__device__ float g_U [N_NODES * 512];
__device__ float g_scal[N_NODES * 4];
__device__ int   g_rowptr[N_NODES + 1];
__device__ int   g_cnt[N_NODES];
__device__ int   g_srcs[E_EDGES];

// ---------------------------------------------------------------------------
// bf16 split helpers: x = hi + lo, both bf16. Kept products: hh + lh + hl
// (drops ll ~ 2^-18 |x||y|) -> fp32-class accuracy for this problem.
// ---------------------------------------------------------------------------
__device__ __forceinline__ void bf16split(float x, uint16_t& hi, uint16_t& lo,
                                          float& hif)
{
    __nv_bfloat16 h = __float2bfloat16_rn(x);
    hif = __bfloat162float(h);
    __nv_bfloat16 l = __float2bfloat16_rn(x - hif);
    hi = __bfloat16_as_ushort(h);
    lo = __bfloat16_as_ushort(l);
}

// mma.sync m16n8k16 bf16 (A row, B col), f32 accumulate
#define MMA_BF16(d, a, b)                                                     \
    asm volatile(                                                             \
        "mma.sync.aligned.m16n8k16.row.col.f32.bf16.bf16.f32 "                \
        "{%0,%1,%2,%3},{%4,%5,%6,%7},{%8,%9},{%0,%1,%2,%3};"                  \
        : "+f"((d)[0]), "+f"((d)[1]), "+f"((d)[2]), "+f"((d)[3])              \
        : "r"((a)[0]), "r"((a)[1]), "r"((a)[2]), "r"((a)[3]),                 \
          "r"((b)[0]), "r"((b)[1]))

// ---------------------------------------------------------------------------
// Tensor-core GEMM (bf16x3): C[M,N] = A[M,K] * B
//   BT=false: B is [K,N] row-major;  BT=true: B is [N,K] row-major (C=A*B^T)
// Block 128x128, BK=32, 256 threads = 8 warps (2x4) of 64x32 warp tiles.
// smem layout: uint32 words of packed bf16x2 (k even/odd), row stride 20
// words (16 data + 4 pad) -> conflict-free fragment loads.
// ---------------------------------------------------------------------------
#define WSTR 20

template <bool BT>
__global__ __launch_bounds__(256, 2)
void mma_gemm(int M, int N, int K,
              const float* __restrict__ A, int lda,
              const float* __restrict__ B, int ldb,
              float* __restrict__ C, int ldc)
{
    __shared__ uint32_t Ah[128 * WSTR];
    __shared__ uint32_t Al[128 * WSTR];
    __shared__ uint32_t Bh[128 * WSTR];
    __shared__ uint32_t Bl[128 * WSTR];

    const int tid  = threadIdx.x;
    const int lane = tid & 31;
    const int wid  = tid >> 5;
    const int g    = lane >> 2;        // 0..7
    const int tig  = lane & 3;         // 0..3
    const int wm   = (wid & 1) * 64;
    const int wn   = (wid >> 1) * 32;
    const int m0   = blockIdx.y * 128;
    const int n0   = blockIdx.x * 128;

    float acc[4][4][4];
#pragma unroll
    for (int i = 0; i < 4; i++)
#pragma unroll
        for (int j = 0; j < 4; j++)
#pragma unroll
            for (int c = 0; c < 4; c++) acc[i][j][c] = 0.f;

    for (int k0 = 0; k0 < K; k0 += 32) {
        // ---- A tile: 128 x 32 floats. 1024 float4-tasks, 4 per thread.
#pragma unroll
        for (int i = 0; i < 4; i++) {
            int t   = i * 256 + tid;
            int row = t >> 3;          // m 0..127
            int q   = t & 7;           // float4 idx, k = q*4
            int gm = m0 + row, gk = k0 + q * 4;
            float4 v = make_float4(0.f, 0.f, 0.f, 0.f);
            if (gm < M) {
                const float* ap = A + (size_t)gm * lda + gk;
                if (gk + 3 < K) v = *reinterpret_cast<const float4*>(ap);
                else {
                    if (gk     < K) v.x = ap[0];
                    if (gk + 1 < K) v.y = ap[1];
                    if (gk + 2 < K) v.z = ap[2];
                    if (gk + 3 < K) v.w = ap[3];
                }
            }
            uint16_t hx, lx, hy, ly, hz, lz, hw, lw; float f;
            bf16split(v.x, hx, lx, f);
            bf16split(v.y, hy, ly, f);
            bf16split(v.z, hz, lz, f);
            bf16split(v.w, hw, lw, f);
            int w = row * WSTR + q * 2;
            Ah[w    ] = (uint32_t)hx | ((uint32_t)hy << 16);
            Ah[w + 1] = (uint32_t)hz | ((uint32_t)hw << 16);
            Al[w    ] = (uint32_t)lx | ((uint32_t)ly << 16);
            Al[w + 1] = (uint32_t)lz | ((uint32_t)lw << 16);
        }
        // ---- B tile -> n-major packed-k words Bs[n][k/2]
        if (!BT) {
            // B[K,N] row-major: thread handles (n, k4); loads coalesced over n
#pragma unroll
            for (int i = 0; i < 4; i++) {
                int t  = i * 256 + tid;
                int nl = t & 127;
                int k4 = t >> 7;           // 0..7
                int gn = n0 + nl;
                float v0 = 0.f, v1 = 0.f, v2 = 0.f, v3 = 0.f;
                if (gn < N) {
                    int gk = k0 + k4 * 4;
                    const float* bp = B + (size_t)gk * ldb + gn;
                    if (gk     < K) v0 = bp[0];
                    if (gk + 1 < K) v1 = bp[(size_t)ldb];
                    if (gk + 2 < K) v2 = bp[(size_t)ldb * 2];
                    if (gk + 3 < K) v3 = bp[(size_t)ldb * 3];
                }
                uint16_t h0, l0, h1, l1, h2, l2, h3, l3; float f;
                bf16split(v0, h0, l0, f);
                bf16split(v1, h1, l1, f);
                bf16split(v2, h2, l2, f);
                bf16split(v3, h3, l3, f);
                int w = nl * WSTR + k4 * 2;
                Bh[w    ] = (uint32_t)h0 | ((uint32_t)h1 << 16);
                Bh[w + 1] = (uint32_t)h2 | ((uint32_t)h3 << 16);
                Bl[w    ] = (uint32_t)l0 | ((uint32_t)l1 << 16);
                Bl[w + 1] = (uint32_t)l2 | ((uint32_t)l3 << 16);
            }
        } else {
            // B[N,K] row-major: same pattern as A
#pragma unroll
            for (int i = 0; i < 4; i++) {
                int t   = i * 256 + tid;
                int row = t >> 3;          // n 0..127
                int q   = t & 7;
                int gn = n0 + row, gk = k0 + q * 4;
                float4 v = make_float4(0.f, 0.f, 0.f, 0.f);
                if (gn < N) {
                    const float* bp = B + (size_t)gn * ldb + gk;
                    if (gk + 3 < K) v = *reinterpret_cast<const float4*>(bp);
                    else {
                        if (gk     < K) v.x = bp[0];
                        if (gk + 1 < K) v.y = bp[1];
                        if (gk + 2 < K) v.z = bp[2];
                        if (gk + 3 < K) v.w = bp[3];
                    }
                }
                uint16_t hx, lx, hy, ly, hz, lz, hw, lw; float f;
                bf16split(v.x, hx, lx, f);
                bf16split(v.y, hy, ly, f);
                bf16split(v.z, hz, lz, f);
                bf16split(v.w, hw, lw, f);
                int w = row * WSTR + q * 2;
                Bh[w    ] = (uint32_t)hx | ((uint32_t)hy << 16);
                Bh[w + 1] = (uint32_t)hz | ((uint32_t)hw << 16);
                Bl[w    ] = (uint32_t)lx | ((uint32_t)ly << 16);
                Bl[w + 1] = (uint32_t)lz | ((uint32_t)lw << 16);
            }
        }
        __syncthreads();

#pragma unroll
        for (int ws = 0; ws < 16; ws += 8) {   // two k16 steps per BK=32
            uint32_t ah[4][4], al[4][4];
#pragma unroll
            for (int mf = 0; mf < 4; mf++) {
                int r1 = (wm + mf * 16 + g) * WSTR + ws;
                int r2 = r1 + 8 * WSTR;
                ah[mf][0] = Ah[r1 + tig];
                ah[mf][1] = Ah[r2 + tig];
                ah[mf][2] = Ah[r1 + tig + 4];
                ah[mf][3] = Ah[r2 + tig + 4];
                al[mf][0] = Al[r1 + tig];
                al[mf][1] = Al[r2 + tig];
                al[mf][2] = Al[r1 + tig + 4];
                al[mf][3] = Al[r2 + tig + 4];
            }
            uint32_t bh[4][2], bl[4][2];
#pragma unroll
            for (int nf = 0; nf < 4; nf++) {
                int r = (wn + nf * 8 + g) * WSTR + ws;
                bh[nf][0] = Bh[r + tig];
                bh[nf][1] = Bh[r + tig + 4];
                bl[nf][0] = Bl[r + tig];
                bl[nf][1] = Bl[r + tig + 4];
            }
            // hh, then lh, then hl: 16 independent MMAs between acc reuses
#pragma unroll
            for (int mf = 0; mf < 4; mf++)
#pragma unroll
                for (int nf = 0; nf < 4; nf++)
                    MMA_BF16(acc[mf][nf], ah[mf], bh[nf]);
#pragma unroll
            for (int mf = 0; mf < 4; mf++)
#pragma unroll
                for (int nf = 0; nf < 4; nf++)
                    MMA_BF16(acc[mf][nf], al[mf], bh[nf]);
#pragma unroll
            for (int mf = 0; mf < 4; mf++)
#pragma unroll
                for (int nf = 0; nf < 4; nf++)
                    MMA_BF16(acc[mf][nf], ah[mf], bl[nf]);
        }
        __syncthreads();
    }

    // ---- Epilogue
#pragma unroll
    for (int mf = 0; mf < 4; mf++) {
        int gm1 = m0 + wm + mf * 16 + g;
        int gm2 = gm1 + 8;
#pragma unroll
        for (int nf = 0; nf < 4; nf++) {
            int gn = n0 + wn + nf * 8 + tig * 2;
            if (gm1 < M) {
                if (gn     < N) C[(size_t)gm1 * ldc + gn    ] = acc[mf][nf][0];
                if (gn + 1 < N) C[(size_t)gm1 * ldc + gn + 1] = acc[mf][nf][1];
            }
            if (gm2 < M) {
                if (gn     < N) C[(size_t)gm2 * ldc + gn    ] = acc[mf][nf][2];
                if (gn + 1 < N) C[(size_t)gm2 * ldc + gn + 1] = acc[mf][nf][3];
            }
        }
    }
}

// ---------------------------------------------------------------------------
// CSR build
// ---------------------------------------------------------------------------
__global__ void hist_kernel(const int* __restrict__ dst, int* cnt, int E)
{
    int i = blockIdx.x * blockDim.x + threadIdx.x;
    if (i < E) atomicAdd(&cnt[dst[i]], 1);
}

__global__ void scan_kernel(const int* counts, int* rowptr, int* cursor, int N, int E)
{
    __shared__ int sm[1024];
    int tid = threadIdx.x;
    int ch  = (N + 1023) / 1024;
    int b   = tid * ch;
    int e   = min(b + ch, N);
    int s = 0;
    for (int i = b; i < e; i++) s += counts[i];
    sm[tid] = s;
    __syncthreads();
    for (int off = 1; off < 1024; off <<= 1) {
        int t = (tid >= off) ? sm[tid - off] : 0;
        __syncthreads();
        sm[tid] += t;
        __syncthreads();
    }
    int run = (tid == 0) ? 0 : sm[tid - 1];
    for (int i = b; i < e; i++) {
        int c = counts[i];
        rowptr[i] = run;
        cursor[i] = run;
        run += c;
    }
    if (tid == 0) rowptr[N] = E;
}

__global__ void fill_kernel(const int* __restrict__ src, const int* __restrict__ dst,
                            int* cursor, int* __restrict__ srcs, int E)
{
    int i = blockIdx.x * blockDim.x + threadIdx.x;
    if (i < E) {
        int p = atomicAdd(&cursor[dst[i]], 1);
        srcs[p] = src[i];
    }
}

// ---------------------------------------------------------------------------
// Per-node attention scalars
// ---------------------------------------------------------------------------
template <int NH>
__global__ void dots_kernel(const float* __restrict__ H,
                            const float* __restrict__ a_src,
                            const float* __restrict__ a_dst,
                            float* __restrict__ es, float* __restrict__ ed, int N)
{
    int gw   = (blockIdx.x * blockDim.x + threadIdx.x) >> 5;
    int lane = threadIdx.x & 31;
    if (gw >= N) return;
    const float* h = H + (size_t)gw * NH;
    float ps = 0.f, pd = 0.f;
#pragma unroll
    for (int c = lane; c < NH; c += 32) {
        float v = h[c];
        ps += v * __ldg(&a_src[c]);
        pd += v * __ldg(&a_dst[c]);
    }
#pragma unroll
    for (int o = 16; o; o >>= 1) {
        ps += __shfl_xor_sync(0xffffffffu, ps, o);
        pd += __shfl_xor_sync(0xffffffffu, pd, o);
    }
    if (lane == 0) { es[gw] = ps; ed[gw] = pd; }
}

// ---------------------------------------------------------------------------
// Fused GAT aggregation (segment softmax + weighted gather + elu)
// ---------------------------------------------------------------------------
template <int NH>
__global__ void gat_agg_kernel(const float* __restrict__ H,
                               const float* __restrict__ es,
                               const float* __restrict__ ed,
                               const int* __restrict__ rowptr,
                               const int* __restrict__ srcs,
                               const int* __restrict__ perm,
                               float* __restrict__ out, int out_ld, int out_off, int N)
{
    constexpr int R4 = NH / 128;
    int gw   = (blockIdx.x * blockDim.x + threadIdx.x) >> 5;
    int lane = threadIdx.x & 31;
    if (gw >= N) return;

    int beg = rowptr[gw], end = rowptr[gw + 1];
    int dsti = perm ? __ldg(&perm[gw]) : gw;
    float edd = __ldg(&ed[dsti]);

    float m = -INFINITY;
    for (int j = beg + lane; j < end; j += 32) {
        int s  = __ldg(&srcs[j]);
        int si = perm ? __ldg(&perm[s]) : s;
        float e = __ldg(&es[si]) + edd;
        e = e > 0.f ? e : 0.2f * e;
        m = fmaxf(m, e);
    }
#pragma unroll
    for (int o = 16; o; o >>= 1) m = fmaxf(m, __shfl_xor_sync(0xffffffffu, m, o));
    if (!isfinite(m)) m = 0.f;

    float4 acc[R4];
#pragma unroll
    for (int c = 0; c < R4; c++) acc[c] = make_float4(0.f, 0.f, 0.f, 0.f);
    float sumw = 0.f;

    for (int j = beg; j < end; ++j) {
        int s  = __ldg(&srcs[j]);
        int si = perm ? __ldg(&perm[s]) : s;
        float e = __ldg(&es[si]) + edd;
        e = e > 0.f ? e : 0.2f * e;
        float w = expf(e - m);
        sumw += w;
        const float4* h4 = reinterpret_cast<const float4*>(H + (size_t)si * NH) + lane;
#pragma unroll
        for (int c = 0; c < R4; c++) {
            float4 v = __ldg(&h4[c * 32]);
            acc[c].x += w * v.x; acc[c].y += w * v.y;
            acc[c].z += w * v.z; acc[c].w += w * v.w;
        }
    }

    float inv = 1.f / (sumw + 1e-16f);
    float4* o4 = reinterpret_cast<float4*>(out + (size_t)gw * out_ld + out_off) + lane;
#pragma unroll
    for (int c = 0; c < R4; c++) {
        float4 v;
        v.x = acc[c].x * inv; v.y = acc[c].y * inv;
        v.z = acc[c].z * inv; v.w = acc[c].w * inv;
        v.x = v.x > 0.f ? v.x : expm1f(v.x);
        v.y = v.y > 0.f ? v.y : expm1f(v.y);
        v.z = v.z > 0.f ? v.z : expm1f(v.z);
        v.w = v.w > 0.f ? v.w : expm1f(v.w);
        o4[c * 32] = v;
    }
}

// ---------------------------------------------------------------------------
// summary = sigmoid(mean(h2, axis=0))
// ---------------------------------------------------------------------------
__global__ void summary_kernel(const float* __restrict__ h2, float* __restrict__ out,
                               int N, int C)
{
    int c   = blockIdx.x;
    int tid = threadIdx.x;
    float s = 0.f;
    for (int r = tid; r < N; r += blockDim.x) s += h2[(size_t)r * C + c];
    __shared__ float sm[256];
    sm[tid] = s;
    __syncthreads();
    for (int o = 128; o; o >>= 1) {
        if (tid < o) sm[tid] += sm[tid + o];
        __syncthreads();
    }
    if (tid == 0) {
        float mval = sm[0] / (float)N;
        out[c] = 1.f / (1.f + expf(-mval));
    }
}

// ---------------------------------------------------------------------------
// Host orchestration
// ---------------------------------------------------------------------------
extern "C" void kernel_launch(void* const* d_in, const int* in_sizes, int n_in,
                              void* d_out, int out_size)
{
    const float* features    = (const float*)d_in[0];
    const float* im_features = (const float*)d_in[1];
    const float* W1x     = (const float*)d_in[2];
    const float* a1x_src = (const float*)d_in[3];
    const float* a1x_dst = (const float*)d_in[4];
    const float* W1r     = (const float*)d_in[5];
    const float* a1r_src = (const float*)d_in[6];
    const float* a1r_dst = (const float*)d_in[7];
    const float* W2      = (const float*)d_in[8];
    const float* a3_src  = (const float*)d_in[9];
    const float* a3_dst  = (const float*)d_in[10];
    const int*   ei      = (const int*)d_in[11];
    const int*   perm    = (const int*)d_in[12];

    const int N   = in_sizes[12];
    const int E   = in_sizes[11] / 2;
    const int NH  = in_sizes[3];
    const int INX = in_sizes[0] / N;
    const int INR = in_sizes[1] / N;
    const int OUT = in_sizes[8] / (2 * NH);

    const int* srcI = ei;
    const int* dstI = ei + E;

    float *Hx, *Hr, *T0, *T1, *U, *scal;
    int *rp, *cnt, *sr;
    cudaGetSymbolAddress((void**)&Hx,  g_Hx);
    cudaGetSymbolAddress((void**)&Hr,  g_Hr);
    cudaGetSymbolAddress((void**)&T0,  g_T0);
    cudaGetSymbolAddress((void**)&T1,  g_T1);
    cudaGetSymbolAddress((void**)&U,   g_U);
    cudaGetSymbolAddress((void**)&scal,g_scal);
    cudaGetSymbolAddress((void**)&rp,  g_rowptr);
    cudaGetSymbolAddress((void**)&cnt, g_cnt);
    cudaGetSymbolAddress((void**)&sr,  g_srcs);

    float* out = (float*)d_out;
    size_t oH2   = 0;
    size_t oH4X  = oH2   + (size_t)N * OUT;
    size_t oH4R  = oH4X  + (size_t)N * INX;
    size_t oRH2  = oH4R  + (size_t)N * INR;
    size_t oRH4X = oRH2  + (size_t)N * OUT;
    size_t oRH4R = oRH4X + (size_t)N * INX;
    size_t oSUM  = oRH4R + (size_t)N * INR;

    auto gg = [](int M, int Nn) { return dim3((unsigned)((Nn + 127) / 128),
                                              (unsigned)((M + 127) / 128)); };
    const int WGRID = (N * 32 + 255) / 256;

    // --- CSR by dst ---
    cudaMemsetAsync(cnt, 0, N * sizeof(int));
    hist_kernel<<<(E + 255) / 256, 256>>>(dstI, cnt, E);
    scan_kernel<<<1, 1024>>>(cnt, rp, cnt, N, E);
    fill_kernel<<<(E + 255) / 256, 256>>>(srcI, dstI, cnt, sr, E);

    // --- Forward projections (shared by orig & perm paths) ---
    mma_gemm<false><<<gg(N, NH), 256>>>(N, NH, INX, features,    INX, W1x, NH, Hx, NH);
    mma_gemm<false><<<gg(N, NH), 256>>>(N, NH, INR, im_features, INR, W1r, NH, Hr, NH);

    // --- Attention scalars ---
    dots_kernel<256><<<WGRID, 256>>>(Hx, a1x_src, a1x_dst, scal + 0 * N, scal + 1 * N, N);
    dots_kernel<256><<<WGRID, 256>>>(Hr, a1r_src, a1r_dst, scal + 2 * N, scal + 3 * N, N);

    // --- Encode aggregation ---
    gat_agg_kernel<256><<<WGRID, 256>>>(Hx, scal + 0 * N, scal + 1 * N, rp, sr, nullptr, T0, 512, 0,   N);
    gat_agg_kernel<256><<<WGRID, 256>>>(Hr, scal + 2 * N, scal + 3 * N, rp, sr, nullptr, T0, 512, 256, N);
    gat_agg_kernel<256><<<WGRID, 256>>>(Hx, scal + 0 * N, scal + 1 * N, rp, sr, perm,    T1, 512, 0,   N);
    gat_agg_kernel<256><<<WGRID, 256>>>(Hr, scal + 2 * N, scal + 3 * N, rp, sr, perm,    T1, 512, 256, N);

    // --- h2 = concat @ W2 ---
    mma_gemm<false><<<gg(N, OUT), 256>>>(N, OUT, 2 * NH, T0, 2 * NH, W2, OUT, out + oH2,  OUT);
    mma_gemm<false><<<gg(N, OUT), 256>>>(N, OUT, 2 * NH, T1, 2 * NH, W2, OUT, out + oRH2, OUT);

    summary_kernel<<<OUT, 256>>>(out + oH2, out + oSUM, N, OUT);

    // --- Decode: orig ---
    mma_gemm<true><<<gg(N, 2 * NH), 256>>>(N, 2 * NH, OUT, out + oH2, OUT, W2, OUT, T0, 2 * NH);
    dots_kernel<512><<<WGRID, 256>>>(T0, a3_src, a3_dst, scal + 0 * N, scal + 1 * N, N);
    gat_agg_kernel<512><<<WGRID, 256>>>(T0, scal + 0 * N, scal + 1 * N, rp, sr, nullptr, U, 512, 0, N);
    mma_gemm<true><<<gg(N, INX), 256>>>(N, INX, NH, U,       512, W1x, NH, out + oH4X, INX);
    mma_gemm<true><<<gg(N, INR), 256>>>(N, INR, NH, U + NH,  512, W1r, NH, out + oH4R, INR);

    // --- Decode: rand ---
    mma_gemm<true><<<gg(N, 2 * NH), 256>>>(N, 2 * NH, OUT, out + oRH2, OUT, W2, OUT, T1, 2 * NH);
    dots_kernel<512><<<WGRID, 256>>>(T1, a3_src, a3_dst, scal + 2 * N, scal + 3 * N, N);
    gat_agg_kernel<512><<<WGRID, 256>>>(T1, scal + 2 * N, scal + 3 * N, rp, sr, nullptr, U, 512, 0, N);
    mma_gemm<true><<<gg(N, INX), 256>>>(N, INX, NH, U,       512, W1x, NH, out + oRH4X, INX);
    mma_gemm<true><<<gg(N, INR), 256>>>(N, INR, NH, U + NH,  512, W1r, NH, out + oRH4R, INR);

    (void)n_in; (void)out_size;
}

// round 5
// speedup vs baseline: 2.5838x; 1.8143x over previous
#include <cuda_runtime.h>
#include <cuda_bf16.h>
#include <math.h>
#include <stdint.h>

// ---------------------------------------------------------------------------
// stGCL: N=30000 nodes, E=480000 edges, IN_X=3000, IN_R=2048, NH=256, OUT=64.
// ---------------------------------------------------------------------------
#define N_NODES  30000
#define E_EDGES  480000
#define KPX      3008          // IN_X padded to multiple of 32

// ---- fp32 scratch ----------------------------------------------------------
__device__ float g_Hx[N_NODES * 256];
__device__ float g_Hr[N_NODES * 256];
__device__ float g_T0[N_NODES * 512];
__device__ float g_T1[N_NODES * 512];
__device__ float g_U [N_NODES * 512];
__device__ float g_scal[N_NODES * 4];
__device__ int   g_rowptr[N_NODES + 1];
__device__ int   g_cnt[N_NODES];
__device__ int   g_srcs[E_EDGES];

// ---- bf16 split scratch (hi/lo pairs) --------------------------------------
__device__ uint16_t g_fx_h[N_NODES * KPX],  g_fx_l[N_NODES * KPX];
__device__ uint16_t g_fr_h[N_NODES * 2048], g_fr_l[N_NODES * 2048];
__device__ uint16_t g_w1xT_h[256 * KPX],    g_w1xT_l[256 * KPX];
__device__ uint16_t g_w1rT_h[256 * 2048],   g_w1rT_l[256 * 2048];
__device__ uint16_t g_w1x_h[3000 * 256],    g_w1x_l[3000 * 256];
__device__ uint16_t g_w1r_h[2048 * 256],    g_w1r_l[2048 * 256];
__device__ uint16_t g_w2T_h[64 * 512],      g_w2T_l[64 * 512];
__device__ uint16_t g_w2_h[512 * 64],       g_w2_l[512 * 64];
__device__ uint16_t g_A2_h[N_NODES * 512],  g_A2_l[N_NODES * 512];
__device__ uint16_t g_AU_h[N_NODES * 512],  g_AU_l[N_NODES * 512];
__device__ uint16_t g_Ah2_h[N_NODES * 64],  g_Ah2_l[N_NODES * 64];

// ---------------------------------------------------------------------------
// bf16 split: x = hi + lo (both bf16); kept products hh+lh+hl
// ---------------------------------------------------------------------------
__device__ __forceinline__ void bsplit(float x, uint16_t& h, uint16_t& l)
{
    __nv_bfloat16 hb = __float2bfloat16_rn(x);
    float hf = __bfloat162float(hb);
    __nv_bfloat16 lb = __float2bfloat16_rn(x - hf);
    h = __bfloat16_as_ushort(hb);
    l = __bfloat16_as_ushort(lb);
}

// ---------------------------------------------------------------------------
// Split kernels
// ---------------------------------------------------------------------------
// fp32 [R,C] -> bf16 hi/lo [R,CP] (zero pad C..CP). C multiple of 4.
__global__ void split_rows_kernel(const float* __restrict__ in, int R, int C, int CP,
                                  uint16_t* __restrict__ hi, uint16_t* __restrict__ lo)
{
    int perRow = CP >> 2;
    int t = blockIdx.x * blockDim.x + threadIdx.x;
    if (t >= R * perRow) return;
    int row = t / perRow;
    int c   = (t - row * perRow) << 2;
    float4 v = make_float4(0.f, 0.f, 0.f, 0.f);
    if (c < C) v = *reinterpret_cast<const float4*>(in + (size_t)row * C + c);
    uint16_t h[4], l[4];
    bsplit(v.x, h[0], l[0]);
    bsplit(v.y, h[1], l[1]);
    bsplit(v.z, h[2], l[2]);
    bsplit(v.w, h[3], l[3]);
    uint2 hp, lp;
    hp.x = (uint32_t)h[0] | ((uint32_t)h[1] << 16);
    hp.y = (uint32_t)h[2] | ((uint32_t)h[3] << 16);
    lp.x = (uint32_t)l[0] | ((uint32_t)l[1] << 16);
    lp.y = (uint32_t)l[2] | ((uint32_t)l[3] << 16);
    *reinterpret_cast<uint2*>(hi + (size_t)row * CP + c) = hp;
    *reinterpret_cast<uint2*>(lo + (size_t)row * CP + c) = lp;
}

// fp32 [R,C] -> transposed bf16 hi/lo [C,RP] (zero pad R..RP)
__global__ void splitT_kernel(const float* __restrict__ in, int R, int C, int RP,
                              uint16_t* __restrict__ hi, uint16_t* __restrict__ lo)
{
    __shared__ float tile[32][33];
    int tx = threadIdx.x & 31;
    int ty = threadIdx.x >> 5;          // 0..7
    int r0 = blockIdx.y * 32;
    int c0 = blockIdx.x * 32;
#pragma unroll
    for (int j = ty; j < 32; j += 8) {
        int r = r0 + j, c = c0 + tx;
        tile[j][tx] = (r < R && c < C) ? in[(size_t)r * C + c] : 0.f;
    }
    __syncthreads();
#pragma unroll
    for (int j = ty; j < 32; j += 8) {
        int oc = c0 + j;      // output row (= original col)
        int orr = r0 + tx;    // output col (= original row)
        if (oc < C && orr < RP) {
            uint16_t h, l;
            bsplit(tile[tx][j], h, l);
            hi[(size_t)oc * RP + orr] = h;
            lo[(size_t)oc * RP + orr] = l;
        }
    }
}

// ---------------------------------------------------------------------------
// mma m16n8k16 bf16
// ---------------------------------------------------------------------------
#define MMA_BF16(d, a, b)                                                     \
    asm volatile(                                                             \
        "mma.sync.aligned.m16n8k16.row.col.f32.bf16.bf16.f32 "                \
        "{%0,%1,%2,%3},{%4,%5,%6,%7},{%8,%9},{%0,%1,%2,%3};"                  \
        : "+f"((d)[0]), "+f"((d)[1]), "+f"((d)[2]), "+f"((d)[3])              \
        : "r"((a)[0]), "r"((a)[1]), "r"((a)[2]), "r"((a)[3]),                 \
          "r"((b)[0]), "r"((b)[1]))

#define WSTR   20                 // words per smem row (16 data + 4 pad)
#define TILE_W (128 * WSTR)       // words per 128x32 bf16 tile
#define STG    (4 * TILE_W)       // words per pipeline stage (Ah,Al,Bh,Bl)
#define GEMM_SMEM (2 * STG * 4)   // bytes

// 16B cp.async of one chunk; 2 chunks/thread per tile
__device__ __forceinline__ void copy_tile_async(
    uint32_t s_byte_base, const uint16_t* __restrict__ g, int ld,
    int row0, int rowmax, int k0, int tid)
{
#pragma unroll
    for (int i = 0; i < 2; i++) {
        int ch  = tid * 2 + i;          // 0..511
        int row = ch >> 2;              // 0..127
        int c   = ch & 3;               // 16B chunk within 64B row
        int gr  = row0 + row;
        if (gr > rowmax) gr = rowmax;
        const uint16_t* src = g + (size_t)gr * ld + k0 + c * 8;
        uint32_t dst = s_byte_base + (uint32_t)(row * WSTR + c * 4) * 4u;
        asm volatile("cp.async.cg.shared.global [%0], [%1], 16;"
                     :: "r"(dst), "l"(src) : "memory");
    }
}

// ---------------------------------------------------------------------------
// bf16x3 GEMM, both operands pre-split bf16, K-major:
//   C[M,N] = (Ahi+Alo)[M,K] * (Bhi+Blo)[N,K]^T   (keeping hh+lh+hl)
// 128x128 block, BK=32, 256 threads, double-buffered cp.async pipeline.
// Requires: K % 32 == 0, lda/ldb % 8 == 0.
// ---------------------------------------------------------------------------
__global__ __launch_bounds__(256, 2)
void mma_gemm_bf16(int M, int N, int K,
                   const uint16_t* __restrict__ Ahi, const uint16_t* __restrict__ Alo, int lda,
                   const uint16_t* __restrict__ Bhi, const uint16_t* __restrict__ Blo, int ldb,
                   float* __restrict__ C, int ldc)
{
    extern __shared__ uint32_t smem[];
    const uint32_t sb = (uint32_t)__cvta_generic_to_shared(smem);

    const int tid  = threadIdx.x;
    const int lane = tid & 31;
    const int wid  = tid >> 5;
    const int g    = lane >> 2;
    const int tig  = lane & 3;
    const int wm   = (wid & 1) * 64;
    const int wn   = (wid >> 1) * 32;
    const int m0   = blockIdx.y * 128;
    const int n0   = blockIdx.x * 128;
    const int nk   = K >> 5;

    float acc[4][4][4];
#pragma unroll
    for (int i = 0; i < 4; i++)
#pragma unroll
        for (int j = 0; j < 4; j++)
#pragma unroll
            for (int c = 0; c < 4; c++) acc[i][j][c] = 0.f;

    auto load = [&](int s, int kt) {
        int k0 = kt << 5;
        uint32_t base = sb + (uint32_t)(s * STG) * 4u;
        copy_tile_async(base,                Ahi, lda, m0, M - 1, k0, tid);
        copy_tile_async(base + TILE_W * 4,   Alo, lda, m0, M - 1, k0, tid);
        copy_tile_async(base + 2 * TILE_W * 4, Bhi, ldb, n0, N - 1, k0, tid);
        copy_tile_async(base + 3 * TILE_W * 4, Blo, ldb, n0, N - 1, k0, tid);
    };

    load(0, 0);
    asm volatile("cp.async.commit_group;" ::: "memory");

    int cur = 0;
    for (int kt = 0; kt < nk; kt++) {
        if (kt + 1 < nk) load(cur ^ 1, kt + 1);
        asm volatile("cp.async.commit_group;" ::: "memory");
        asm volatile("cp.async.wait_group 1;" ::: "memory");
        __syncthreads();

        const uint32_t* Ah = smem + cur * STG;
        const uint32_t* Al = Ah + TILE_W;
        const uint32_t* Bh = Al + TILE_W;
        const uint32_t* Bl = Bh + TILE_W;

#pragma unroll
        for (int ws = 0; ws < 16; ws += 8) {     // two k16 steps
            uint32_t ah[4][4], al[4][4];
#pragma unroll
            for (int mf = 0; mf < 4; mf++) {
                int r1 = (wm + mf * 16 + g) * WSTR + ws;
                int r2 = r1 + 8 * WSTR;
                ah[mf][0] = Ah[r1 + tig];
                ah[mf][1] = Ah[r2 + tig];
                ah[mf][2] = Ah[r1 + tig + 4];
                ah[mf][3] = Ah[r2 + tig + 4];
                al[mf][0] = Al[r1 + tig];
                al[mf][1] = Al[r2 + tig];
                al[mf][2] = Al[r1 + tig + 4];
                al[mf][3] = Al[r2 + tig + 4];
            }
            uint32_t bh[4][2], bl[4][2];
#pragma unroll
            for (int nf = 0; nf < 4; nf++) {
                int r = (wn + nf * 8 + g) * WSTR + ws;
                bh[nf][0] = Bh[r + tig];
                bh[nf][1] = Bh[r + tig + 4];
                bl[nf][0] = Bl[r + tig];
                bl[nf][1] = Bl[r + tig + 4];
            }
#pragma unroll
            for (int mf = 0; mf < 4; mf++)
#pragma unroll
                for (int nf = 0; nf < 4; nf++)
                    MMA_BF16(acc[mf][nf], ah[mf], bh[nf]);
#pragma unroll
            for (int mf = 0; mf < 4; mf++)
#pragma unroll
                for (int nf = 0; nf < 4; nf++)
                    MMA_BF16(acc[mf][nf], al[mf], bh[nf]);
#pragma unroll
            for (int mf = 0; mf < 4; mf++)
#pragma unroll
                for (int nf = 0; nf < 4; nf++)
                    MMA_BF16(acc[mf][nf], ah[mf], bl[nf]);
        }
        __syncthreads();
        cur ^= 1;
    }

    // ---- Epilogue
#pragma unroll
    for (int mf = 0; mf < 4; mf++) {
        int gm1 = m0 + wm + mf * 16 + g;
        int gm2 = gm1 + 8;
#pragma unroll
        for (int nf = 0; nf < 4; nf++) {
            int gn = n0 + wn + nf * 8 + tig * 2;
            if (gm1 < M) {
                if (gn     < N) C[(size_t)gm1 * ldc + gn    ] = acc[mf][nf][0];
                if (gn + 1 < N) C[(size_t)gm1 * ldc + gn + 1] = acc[mf][nf][1];
            }
            if (gm2 < M) {
                if (gn     < N) C[(size_t)gm2 * ldc + gn    ] = acc[mf][nf][2];
                if (gn + 1 < N) C[(size_t)gm2 * ldc + gn + 1] = acc[mf][nf][3];
            }
        }
    }
}

// ---------------------------------------------------------------------------
// CSR build
// ---------------------------------------------------------------------------
__global__ void hist_kernel(const int* __restrict__ dst, int* cnt, int E)
{
    int i = blockIdx.x * blockDim.x + threadIdx.x;
    if (i < E) atomicAdd(&cnt[dst[i]], 1);
}

__global__ void scan_kernel(const int* counts, int* rowptr, int* cursor, int N, int E)
{
    __shared__ int sm[1024];
    int tid = threadIdx.x;
    int ch  = (N + 1023) / 1024;
    int b   = tid * ch;
    int e   = min(b + ch, N);
    int s = 0;
    for (int i = b; i < e; i++) s += counts[i];
    sm[tid] = s;
    __syncthreads();
    for (int off = 1; off < 1024; off <<= 1) {
        int t = (tid >= off) ? sm[tid - off] : 0;
        __syncthreads();
        sm[tid] += t;
        __syncthreads();
    }
    int run = (tid == 0) ? 0 : sm[tid - 1];
    for (int i = b; i < e; i++) {
        int c = counts[i];
        rowptr[i] = run;
        cursor[i] = run;
        run += c;
    }
    if (tid == 0) rowptr[N] = E;
}

__global__ void fill_kernel(const int* __restrict__ src, const int* __restrict__ dst,
                            int* cursor, int* __restrict__ srcs, int E)
{
    int i = blockIdx.x * blockDim.x + threadIdx.x;
    if (i < E) {
        int p = atomicAdd(&cursor[dst[i]], 1);
        srcs[p] = src[i];
    }
}

// ---------------------------------------------------------------------------
// Per-node attention scalars
// ---------------------------------------------------------------------------
template <int NH>
__global__ void dots_kernel(const float* __restrict__ H,
                            const float* __restrict__ a_src,
                            const float* __restrict__ a_dst,
                            float* __restrict__ es, float* __restrict__ ed, int N)
{
    int gw   = (blockIdx.x * blockDim.x + threadIdx.x) >> 5;
    int lane = threadIdx.x & 31;
    if (gw >= N) return;
    const float* h = H + (size_t)gw * NH;
    float ps = 0.f, pd = 0.f;
#pragma unroll
    for (int c = lane; c < NH; c += 32) {
        float v = h[c];
        ps += v * __ldg(&a_src[c]);
        pd += v * __ldg(&a_dst[c]);
    }
#pragma unroll
    for (int o = 16; o; o >>= 1) {
        ps += __shfl_xor_sync(0xffffffffu, ps, o);
        pd += __shfl_xor_sync(0xffffffffu, pd, o);
    }
    if (lane == 0) { es[gw] = ps; ed[gw] = pd; }
}

// ---------------------------------------------------------------------------
// Fused GAT aggregation (segment softmax + weighted gather + elu)
// ---------------------------------------------------------------------------
template <int NH>
__global__ void gat_agg_kernel(const float* __restrict__ H,
                               const float* __restrict__ es,
                               const float* __restrict__ ed,
                               const int* __restrict__ rowptr,
                               const int* __restrict__ srcs,
                               const int* __restrict__ perm,
                               float* __restrict__ out, int out_ld, int out_off, int N)
{
    constexpr int R4 = NH / 128;
    int gw   = (blockIdx.x * blockDim.x + threadIdx.x) >> 5;
    int lane = threadIdx.x & 31;
    if (gw >= N) return;

    int beg = rowptr[gw], end = rowptr[gw + 1];
    int dsti = perm ? __ldg(&perm[gw]) : gw;
    float edd = __ldg(&ed[dsti]);

    float m = -INFINITY;
    for (int j = beg + lane; j < end; j += 32) {
        int s  = __ldg(&srcs[j]);
        int si = perm ? __ldg(&perm[s]) : s;
        float e = __ldg(&es[si]) + edd;
        e = e > 0.f ? e : 0.2f * e;
        m = fmaxf(m, e);
    }
#pragma unroll
    for (int o = 16; o; o >>= 1) m = fmaxf(m, __shfl_xor_sync(0xffffffffu, m, o));
    if (!isfinite(m)) m = 0.f;

    float4 acc[R4];
#pragma unroll
    for (int c = 0; c < R4; c++) acc[c] = make_float4(0.f, 0.f, 0.f, 0.f);
    float sumw = 0.f;

    for (int j = beg; j < end; ++j) {
        int s  = __ldg(&srcs[j]);
        int si = perm ? __ldg(&perm[s]) : s;
        float e = __ldg(&es[si]) + edd;
        e = e > 0.f ? e : 0.2f * e;
        float w = expf(e - m);
        sumw += w;
        const float4* h4 = reinterpret_cast<const float4*>(H + (size_t)si * NH) + lane;
#pragma unroll
        for (int c = 0; c < R4; c++) {
            float4 v = __ldg(&h4[c * 32]);
            acc[c].x += w * v.x; acc[c].y += w * v.y;
            acc[c].z += w * v.z; acc[c].w += w * v.w;
        }
    }

    float inv = 1.f / (sumw + 1e-16f);
    float4* o4 = reinterpret_cast<float4*>(out + (size_t)gw * out_ld + out_off) + lane;
#pragma unroll
    for (int c = 0; c < R4; c++) {
        float4 v;
        v.x = acc[c].x * inv; v.y = acc[c].y * inv;
        v.z = acc[c].z * inv; v.w = acc[c].w * inv;
        v.x = v.x > 0.f ? v.x : expm1f(v.x);
        v.y = v.y > 0.f ? v.y : expm1f(v.y);
        v.z = v.z > 0.f ? v.z : expm1f(v.z);
        v.w = v.w > 0.f ? v.w : expm1f(v.w);
        o4[c * 32] = v;
    }
}

// ---------------------------------------------------------------------------
// summary = sigmoid(mean(h2, axis=0))
// ---------------------------------------------------------------------------
__global__ void summary_kernel(const float* __restrict__ h2, float* __restrict__ out,
                               int N, int C)
{
    int c   = blockIdx.x;
    int tid = threadIdx.x;
    float s = 0.f;
    for (int r = tid; r < N; r += blockDim.x) s += h2[(size_t)r * C + c];
    __shared__ float sm[256];
    sm[tid] = s;
    __syncthreads();
    for (int o = 128; o; o >>= 1) {
        if (tid < o) sm[tid] += sm[tid + o];
        __syncthreads();
    }
    if (tid == 0) {
        float mval = sm[0] / (float)N;
        out[c] = 1.f / (1.f + expf(-mval));
    }
}

// ---------------------------------------------------------------------------
// Host orchestration
// ---------------------------------------------------------------------------
extern "C" void kernel_launch(void* const* d_in, const int* in_sizes, int n_in,
                              void* d_out, int out_size)
{
    const float* features    = (const float*)d_in[0];
    const float* im_features = (const float*)d_in[1];
    const float* W1x     = (const float*)d_in[2];
    const float* a1x_src = (const float*)d_in[3];
    const float* a1x_dst = (const float*)d_in[4];
    const float* W1r     = (const float*)d_in[5];
    const float* a1r_src = (const float*)d_in[6];
    const float* a1r_dst = (const float*)d_in[7];
    const float* W2      = (const float*)d_in[8];
    const float* a3_src  = (const float*)d_in[9];
    const float* a3_dst  = (const float*)d_in[10];
    const int*   ei      = (const int*)d_in[11];
    const int*   perm    = (const int*)d_in[12];

    const int N   = in_sizes[12];          // 30000
    const int E   = in_sizes[11] / 2;      // 480000
    const int NH  = in_sizes[3];           // 256
    const int INX = in_sizes[0] / N;       // 3000
    const int INR = in_sizes[1] / N;       // 2048
    const int OUT = in_sizes[8] / (2 * NH);// 64

    const int* srcI = ei;
    const int* dstI = ei + E;

    float *Hx, *Hr, *T0, *T1, *U, *scal;
    int *rp, *cnt, *sr;
    cudaGetSymbolAddress((void**)&Hx,  g_Hx);
    cudaGetSymbolAddress((void**)&Hr,  g_Hr);
    cudaGetSymbolAddress((void**)&T0,  g_T0);
    cudaGetSymbolAddress((void**)&T1,  g_T1);
    cudaGetSymbolAddress((void**)&U,   g_U);
    cudaGetSymbolAddress((void**)&scal,g_scal);
    cudaGetSymbolAddress((void**)&rp,  g_rowptr);
    cudaGetSymbolAddress((void**)&cnt, g_cnt);
    cudaGetSymbolAddress((void**)&sr,  g_srcs);

    uint16_t *fxh, *fxl, *frh, *frl, *w1xTh, *w1xTl, *w1rTh, *w1rTl;
    uint16_t *w1xh, *w1xl, *w1rh, *w1rl, *w2Th, *w2Tl, *w2h, *w2l;
    uint16_t *A2h, *A2l, *AUh, *AUl, *Ah2h, *Ah2l;
    cudaGetSymbolAddress((void**)&fxh,  g_fx_h);   cudaGetSymbolAddress((void**)&fxl,  g_fx_l);
    cudaGetSymbolAddress((void**)&frh,  g_fr_h);   cudaGetSymbolAddress((void**)&frl,  g_fr_l);
    cudaGetSymbolAddress((void**)&w1xTh,g_w1xT_h); cudaGetSymbolAddress((void**)&w1xTl,g_w1xT_l);
    cudaGetSymbolAddress((void**)&w1rTh,g_w1rT_h); cudaGetSymbolAddress((void**)&w1rTl,g_w1rT_l);
    cudaGetSymbolAddress((void**)&w1xh, g_w1x_h);  cudaGetSymbolAddress((void**)&w1xl, g_w1x_l);
    cudaGetSymbolAddress((void**)&w1rh, g_w1r_h);  cudaGetSymbolAddress((void**)&w1rl, g_w1r_l);
    cudaGetSymbolAddress((void**)&w2Th, g_w2T_h);  cudaGetSymbolAddress((void**)&w2Tl, g_w2T_l);
    cudaGetSymbolAddress((void**)&w2h,  g_w2_h);   cudaGetSymbolAddress((void**)&w2l,  g_w2_l);
    cudaGetSymbolAddress((void**)&A2h,  g_A2_h);   cudaGetSymbolAddress((void**)&A2l,  g_A2_l);
    cudaGetSymbolAddress((void**)&AUh,  g_AU_h);   cudaGetSymbolAddress((void**)&AUl,  g_AU_l);
    cudaGetSymbolAddress((void**)&Ah2h, g_Ah2_h);  cudaGetSymbolAddress((void**)&Ah2l, g_Ah2_l);

    cudaFuncSetAttribute(mma_gemm_bf16,
                         cudaFuncAttributeMaxDynamicSharedMemorySize, GEMM_SMEM);

    float* out = (float*)d_out;
    size_t oH2   = 0;
    size_t oH4X  = oH2   + (size_t)N * OUT;
    size_t oH4R  = oH4X  + (size_t)N * INX;
    size_t oRH2  = oH4R  + (size_t)N * INR;
    size_t oRH4X = oRH2  + (size_t)N * OUT;
    size_t oRH4R = oRH4X + (size_t)N * INX;
    size_t oSUM  = oRH4R + (size_t)N * INR;

    auto gg = [](int M, int Nn) { return dim3((unsigned)((Nn + 127) / 128),
                                              (unsigned)((M + 127) / 128)); };
    auto sg = [](int R, int CP) { return (unsigned)(((size_t)R * (CP / 4) + 255) / 256); };
    const int WGRID = (N * 32 + 255) / 256;

    // --- CSR by dst ---
    cudaMemsetAsync(cnt, 0, N * sizeof(int));
    hist_kernel<<<(E + 255) / 256, 256>>>(dstI, cnt, E);
    scan_kernel<<<1, 1024>>>(cnt, rp, cnt, N, E);
    fill_kernel<<<(E + 255) / 256, 256>>>(srcI, dstI, cnt, sr, E);

    // --- Splits of inputs / weights ---
    split_rows_kernel<<<sg(N, KPX),  256>>>(features,    N, INX, KPX,  fxh, fxl);
    split_rows_kernel<<<sg(N, INR),  256>>>(im_features, N, INR, INR,  frh, frl);
    split_rows_kernel<<<sg(INX, NH), 256>>>(W1x, INX, NH, NH, w1xh, w1xl);
    split_rows_kernel<<<sg(INR, NH), 256>>>(W1r, INR, NH, NH, w1rh, w1rl);
    split_rows_kernel<<<sg(2*NH, OUT), 256>>>(W2, 2*NH, OUT, OUT, w2h, w2l);
    splitT_kernel<<<dim3((NH  + 31)/32, (KPX  + 31)/32), 256>>>(W1x, INX, NH, KPX, w1xTh, w1xTl);
    splitT_kernel<<<dim3((NH  + 31)/32, (INR  + 31)/32), 256>>>(W1r, INR, NH, INR, w1rTh, w1rTl);
    splitT_kernel<<<dim3((OUT + 31)/32, (2*NH + 31)/32), 256>>>(W2, 2*NH, OUT, 2*NH, w2Th, w2Tl);

    // --- Forward projections ---
    mma_gemm_bf16<<<gg(N, NH), 256, GEMM_SMEM>>>(N, NH, KPX, fxh, fxl, KPX,
                                                 w1xTh, w1xTl, KPX, Hx, NH);
    mma_gemm_bf16<<<gg(N, NH), 256, GEMM_SMEM>>>(N, NH, INR, frh, frl, INR,
                                                 w1rTh, w1rTl, INR, Hr, NH);

    // --- Attention scalars + encode aggregation ---
    dots_kernel<256><<<WGRID, 256>>>(Hx, a1x_src, a1x_dst, scal + 0 * N, scal + 1 * N, N);
    dots_kernel<256><<<WGRID, 256>>>(Hr, a1r_src, a1r_dst, scal + 2 * N, scal + 3 * N, N);
    gat_agg_kernel<256><<<WGRID, 256>>>(Hx, scal + 0 * N, scal + 1 * N, rp, sr, nullptr, T0, 512, 0,   N);
    gat_agg_kernel<256><<<WGRID, 256>>>(Hr, scal + 2 * N, scal + 3 * N, rp, sr, nullptr, T0, 512, 256, N);
    gat_agg_kernel<256><<<WGRID, 256>>>(Hx, scal + 0 * N, scal + 1 * N, rp, sr, perm,    T1, 512, 0,   N);
    gat_agg_kernel<256><<<WGRID, 256>>>(Hr, scal + 2 * N, scal + 3 * N, rp, sr, perm,    T1, 512, 256, N);

    // --- h2 = concat @ W2 ---
    split_rows_kernel<<<sg(N, 2*NH), 256>>>(T0, N, 2*NH, 2*NH, A2h, A2l);
    mma_gemm_bf16<<<gg(N, OUT), 256, GEMM_SMEM>>>(N, OUT, 2*NH, A2h, A2l, 2*NH,
                                                  w2Th, w2Tl, 2*NH, out + oH2, OUT);
    split_rows_kernel<<<sg(N, 2*NH), 256>>>(T1, N, 2*NH, 2*NH, A2h, A2l);
    mma_gemm_bf16<<<gg(N, OUT), 256, GEMM_SMEM>>>(N, OUT, 2*NH, A2h, A2l, 2*NH,
                                                  w2Th, w2Tl, 2*NH, out + oRH2, OUT);

    summary_kernel<<<OUT, 256>>>(out + oH2, out + oSUM, N, OUT);

    // --- Decode: orig ---
    split_rows_kernel<<<sg(N, OUT), 256>>>(out + oH2, N, OUT, OUT, Ah2h, Ah2l);
    mma_gemm_bf16<<<gg(N, 2*NH), 256, GEMM_SMEM>>>(N, 2*NH, OUT, Ah2h, Ah2l, OUT,
                                                   w2h, w2l, OUT, T0, 2*NH);
    dots_kernel<512><<<WGRID, 256>>>(T0, a3_src, a3_dst, scal + 0 * N, scal + 1 * N, N);
    gat_agg_kernel<512><<<WGRID, 256>>>(T0, scal + 0 * N, scal + 1 * N, rp, sr, nullptr, U, 512, 0, N);
    split_rows_kernel<<<sg(N, 2*NH), 256>>>(U, N, 2*NH, 2*NH, AUh, AUl);
    mma_gemm_bf16<<<gg(N, INX), 256, GEMM_SMEM>>>(N, INX, NH, AUh, AUl, 2*NH,
                                                  w1xh, w1xl, NH, out + oH4X, INX);
    mma_gemm_bf16<<<gg(N, INR), 256, GEMM_SMEM>>>(N, INR, NH, AUh + NH, AUl + NH, 2*NH,
                                                  w1rh, w1rl, NH, out + oH4R, INR);

    // --- Decode: rand ---
    split_rows_kernel<<<sg(N, OUT), 256>>>(out + oRH2, N, OUT, OUT, Ah2h, Ah2l);
    mma_gemm_bf16<<<gg(N, 2*NH), 256, GEMM_SMEM>>>(N, 2*NH, OUT, Ah2h, Ah2l, OUT,
                                                   w2h, w2l, OUT, T1, 2*NH);
    dots_kernel<512><<<WGRID, 256>>>(T1, a3_src, a3_dst, scal + 2 * N, scal + 3 * N, N);
    gat_agg_kernel<512><<<WGRID, 256>>>(T1, scal + 2 * N, scal + 3 * N, rp, sr, nullptr, U, 512, 0, N);
    split_rows_kernel<<<sg(N, 2*NH), 256>>>(U, N, 2*NH, 2*NH, AUh, AUl);
    mma_gemm_bf16<<<gg(N, INX), 256, GEMM_SMEM>>>(N, INX, NH, AUh, AUl, 2*NH,
                                                  w1xh, w1xl, NH, out + oRH4X, INX);
    mma_gemm_bf16<<<gg(N, INR), 256, GEMM_SMEM>>>(N, INR, NH, AUh + NH, AUl + NH, 2*NH,
                                                  w1rh, w1rl, NH, out + oRH4R, INR);

    (void)n_in; (void)out_size;
}

// round 9
// speedup vs baseline: 2.5910x; 1.0028x over previous
#include <cuda_runtime.h>
#include <cuda_bf16.h>
#include <math.h>
#include <stdint.h>

// ---------------------------------------------------------------------------
// stGCL: N=30000 nodes, E=480000 edges, IN_X=3000, IN_R=2048, NH=256, OUT=64.
// ---------------------------------------------------------------------------
#define N_NODES  30000
#define E_EDGES  480000
#define KPX      3008          // IN_X padded to multiple of 32

// ---- fp32 scratch ----------------------------------------------------------
__device__ float g_Hx[N_NODES * 256];
__device__ float g_Hr[N_NODES * 256];
__device__ float g_T0[N_NODES * 512];
__device__ float g_T1[N_NODES * 512];
__device__ float g_scal[N_NODES * 4];
__device__ int   g_rowptr[N_NODES + 1];
__device__ int   g_cnt[N_NODES];
__device__ int   g_srcs[E_EDGES];

// ---- bf16 split scratch (hi/lo pairs) --------------------------------------
__device__ uint16_t g_fx_h[N_NODES * KPX],  g_fx_l[N_NODES * KPX];
__device__ uint16_t g_fr_h[N_NODES * 2048], g_fr_l[N_NODES * 2048];
__device__ uint16_t g_w1xT_h[256 * KPX],    g_w1xT_l[256 * KPX];
__device__ uint16_t g_w1rT_h[256 * 2048],   g_w1rT_l[256 * 2048];
__device__ uint16_t g_w1x_h[3000 * 256],    g_w1x_l[3000 * 256];
__device__ uint16_t g_w1r_h[2048 * 256],    g_w1r_l[2048 * 256];
__device__ uint16_t g_w2T_h[64 * 512],      g_w2T_l[64 * 512];
__device__ uint16_t g_w2_h[512 * 64],       g_w2_l[512 * 64];
__device__ uint16_t g_A2_h[N_NODES * 512],  g_A2_l[N_NODES * 512];   // concat(T0) split
__device__ uint16_t g_B2_h[N_NODES * 512],  g_B2_l[N_NODES * 512];   // concat(T1) split
__device__ uint16_t g_AU_h[N_NODES * 512],  g_AU_l[N_NODES * 512];   // h3 split
__device__ uint16_t g_Ah2_h[N_NODES * 64],  g_Ah2_l[N_NODES * 64];   // h2 split

// ---------------------------------------------------------------------------
// bf16 split: x = hi + lo (both bf16); kept products hh+lh+hl
// ---------------------------------------------------------------------------
__device__ __forceinline__ void bsplit(float x, uint16_t& h, uint16_t& l)
{
    __nv_bfloat16 hb = __float2bfloat16_rn(x);
    float hf = __bfloat162float(hb);
    __nv_bfloat16 lb = __float2bfloat16_rn(x - hf);
    h = __bfloat16_as_ushort(hb);
    l = __bfloat16_as_ushort(lb);
}

// mma m16n8k16 bf16, fp32 accum
#define MMA_BF16(d, a, b)                                                     \
    asm volatile(                                                             \
        "mma.sync.aligned.m16n8k16.row.col.f32.bf16.bf16.f32 "                \
        "{%0,%1,%2,%3},{%4,%5,%6,%7},{%8,%9},{%0,%1,%2,%3};"                  \
        : "+f"((d)[0]), "+f"((d)[1]), "+f"((d)[2]), "+f"((d)[3])              \
        : "r"((a)[0]), "r"((a)[1]), "r"((a)[2]), "r"((a)[3]),                 \
          "r"((b)[0]), "r"((b)[1]))

#define WSTR   20                 // words per smem row (16 data + 4 pad)
#define TILE_W (128 * WSTR)       // words per 128x32 bf16 tile
#define STG    (4 * TILE_W)       // words per pipeline stage (Ah,Al,Bh,Bl)
#define GEMM_SMEM (2 * STG * 4)   // bytes

// 16B cp.async of one chunk; 2 chunks/thread per tile
__device__ __forceinline__ void copy_tile_async(
    uint32_t s_byte_base, const uint16_t* __restrict__ g, int ld,
    int row0, int rowmax, int k0, int tid)
{
#pragma unroll
    for (int i = 0; i < 2; i++) {
        int ch  = tid * 2 + i;          // 0..511
        int row = ch >> 2;              // 0..127
        int c   = ch & 3;               // 16B chunk within 64B row
        int gr  = row0 + row;
        if (gr > rowmax) gr = rowmax;
        const uint16_t* src = g + (size_t)gr * ld + k0 + c * 8;
        uint32_t dst = s_byte_base + (uint32_t)(row * WSTR + c * 4) * 4u;
        asm volatile("cp.async.cg.shared.global [%0], [%1], 16;"
                     :: "r"(dst), "l"(src) : "memory");
    }
}

// ---------------------------------------------------------------------------
// bf16x3 GEMM, both operands pre-split bf16, K-major:
//   C[M,N] = (Ahi+Alo)[M,K] * (Bhi+Blo)[N,K]^T   (keeping hh+lh+hl)
// 128x128 block, BK=32, 256 threads, double-buffered cp.async pipeline.
// Optional fused bf16-split of C into (Chi, Clo).
// Requires: K % 32 == 0, lda/ldb % 8 == 0.
// ---------------------------------------------------------------------------
__global__ __launch_bounds__(256, 2)
void mma_gemm_bf16(int M, int N, int K,
                   const uint16_t* __restrict__ Ahi, const uint16_t* __restrict__ Alo, int lda,
                   const uint16_t* __restrict__ Bhi, const uint16_t* __restrict__ Blo, int ldb,
                   float* __restrict__ C, int ldc,
                   uint16_t* __restrict__ Chi, uint16_t* __restrict__ Clo)
{
    extern __shared__ uint32_t smem[];
    const uint32_t sb = (uint32_t)__cvta_generic_to_shared(smem);

    const int tid  = threadIdx.x;
    const int lane = tid & 31;
    const int wid  = tid >> 5;
    const int g    = lane >> 2;
    const int tig  = lane & 3;
    const int wm   = (wid & 1) * 64;
    const int wn   = (wid >> 1) * 32;
    const int m0   = blockIdx.y * 128;
    const int n0   = blockIdx.x * 128;
    const int nk   = K >> 5;

    float acc[4][4][4];
#pragma unroll
    for (int i = 0; i < 4; i++)
#pragma unroll
        for (int j = 0; j < 4; j++)
#pragma unroll
            for (int c = 0; c < 4; c++) acc[i][j][c] = 0.f;

    auto load = [&](int s, int kt) {
        int k0 = kt << 5;
        uint32_t base = sb + (uint32_t)(s * STG) * 4u;
        copy_tile_async(base,                  Ahi, lda, m0, M - 1, k0, tid);
        copy_tile_async(base + TILE_W * 4,     Alo, lda, m0, M - 1, k0, tid);
        copy_tile_async(base + 2 * TILE_W * 4, Bhi, ldb, n0, N - 1, k0, tid);
        copy_tile_async(base + 3 * TILE_W * 4, Blo, ldb, n0, N - 1, k0, tid);
    };

    load(0, 0);
    asm volatile("cp.async.commit_group;" ::: "memory");

    int cur = 0;
    for (int kt = 0; kt < nk; kt++) {
        if (kt + 1 < nk) load(cur ^ 1, kt + 1);
        asm volatile("cp.async.commit_group;" ::: "memory");
        asm volatile("cp.async.wait_group 1;" ::: "memory");
        __syncthreads();

        const uint32_t* Ah = smem + cur * STG;
        const uint32_t* Al = Ah + TILE_W;
        const uint32_t* Bh = Al + TILE_W;
        const uint32_t* Bl = Bh + TILE_W;

#pragma unroll
        for (int ws = 0; ws < 16; ws += 8) {     // two k16 steps per BK=32
            uint32_t ah[4][4], al[4][4];
#pragma unroll
            for (int mf = 0; mf < 4; mf++) {
                int r1 = (wm + mf * 16 + g) * WSTR + ws;
                int r2 = r1 + 8 * WSTR;
                ah[mf][0] = Ah[r1 + tig];
                ah[mf][1] = Ah[r2 + tig];
                ah[mf][2] = Ah[r1 + tig + 4];
                ah[mf][3] = Ah[r2 + tig + 4];
                al[mf][0] = Al[r1 + tig];
                al[mf][1] = Al[r2 + tig];
                al[mf][2] = Al[r1 + tig + 4];
                al[mf][3] = Al[r2 + tig + 4];
            }
            uint32_t bh[4][2], bl[4][2];
#pragma unroll
            for (int nf = 0; nf < 4; nf++) {
                int r = (wn + nf * 8 + g) * WSTR + ws;
                bh[nf][0] = Bh[r + tig];
                bh[nf][1] = Bh[r + tig + 4];
                bl[nf][0] = Bl[r + tig];
                bl[nf][1] = Bl[r + tig + 4];
            }
#pragma unroll
            for (int mf = 0; mf < 4; mf++)
#pragma unroll
                for (int nf = 0; nf < 4; nf++)
                    MMA_BF16(acc[mf][nf], ah[mf], bh[nf]);
#pragma unroll
            for (int mf = 0; mf < 4; mf++)
#pragma unroll
                for (int nf = 0; nf < 4; nf++)
                    MMA_BF16(acc[mf][nf], al[mf], bh[nf]);
#pragma unroll
            for (int mf = 0; mf < 4; mf++)
#pragma unroll
                for (int nf = 0; nf < 4; nf++)
                    MMA_BF16(acc[mf][nf], ah[mf], bl[nf]);
        }
        __syncthreads();
        cur ^= 1;
    }

    // ---- Epilogue (optionally also write bf16 hi/lo split of C)
#pragma unroll
    for (int mf = 0; mf < 4; mf++) {
        int gm1 = m0 + wm + mf * 16 + g;
        int gm2 = gm1 + 8;
#pragma unroll
        for (int nf = 0; nf < 4; nf++) {
            int gn = n0 + wn + nf * 8 + tig * 2;
#pragma unroll
            for (int half = 0; half < 2; half++) {
                int gm = half ? gm2 : gm1;
                if (gm >= M) continue;
                float v0 = acc[mf][nf][half * 2];
                float v1 = acc[mf][nf][half * 2 + 1];
                if (gn < N) {
                    size_t idx = (size_t)gm * ldc + gn;
                    C[idx] = v0;
                    if (Chi) { uint16_t h, l; bsplit(v0, h, l); Chi[idx] = h; Clo[idx] = l; }
                }
                if (gn + 1 < N) {
                    size_t idx = (size_t)gm * ldc + gn + 1;
                    C[idx] = v1;
                    if (Chi) { uint16_t h, l; bsplit(v1, h, l); Chi[idx] = h; Clo[idx] = l; }
                }
            }
        }
    }
}

// ---------------------------------------------------------------------------
// Split kernels (inputs/weights only)
// ---------------------------------------------------------------------------
__global__ void split_rows_kernel(const float* __restrict__ in, int R, int C, int CP,
                                  uint16_t* __restrict__ hi, uint16_t* __restrict__ lo)
{
    int perRow = CP >> 2;
    int t = blockIdx.x * blockDim.x + threadIdx.x;
    if (t >= R * perRow) return;
    int row = t / perRow;
    int c   = (t - row * perRow) << 2;
    float4 v = make_float4(0.f, 0.f, 0.f, 0.f);
    if (c < C) v = *reinterpret_cast<const float4*>(in + (size_t)row * C + c);
    uint16_t h[4], l[4];
    bsplit(v.x, h[0], l[0]);
    bsplit(v.y, h[1], l[1]);
    bsplit(v.z, h[2], l[2]);
    bsplit(v.w, h[3], l[3]);
    uint2 hp, lp;
    hp.x = (uint32_t)h[0] | ((uint32_t)h[1] << 16);
    hp.y = (uint32_t)h[2] | ((uint32_t)h[3] << 16);
    lp.x = (uint32_t)l[0] | ((uint32_t)l[1] << 16);
    lp.y = (uint32_t)l[2] | ((uint32_t)l[3] << 16);
    *reinterpret_cast<uint2*>(hi + (size_t)row * CP + c) = hp;
    *reinterpret_cast<uint2*>(lo + (size_t)row * CP + c) = lp;
}

__global__ void splitT_kernel(const float* __restrict__ in, int R, int C, int RP,
                              uint16_t* __restrict__ hi, uint16_t* __restrict__ lo)
{
    __shared__ float tile[32][33];
    int tx = threadIdx.x & 31;
    int ty = threadIdx.x >> 5;
    int r0 = blockIdx.y * 32;
    int c0 = blockIdx.x * 32;
#pragma unroll
    for (int j = ty; j < 32; j += 8) {
        int r = r0 + j, c = c0 + tx;
        tile[j][tx] = (r < R && c < C) ? in[(size_t)r * C + c] : 0.f;
    }
    __syncthreads();
#pragma unroll
    for (int j = ty; j < 32; j += 8) {
        int oc  = c0 + j;
        int orr = r0 + tx;
        if (oc < C && orr < RP) {
            uint16_t h, l;
            bsplit(tile[tx][j], h, l);
            hi[(size_t)oc * RP + orr] = h;
            lo[(size_t)oc * RP + orr] = l;
        }
    }
}

// ---------------------------------------------------------------------------
// CSR build
// ---------------------------------------------------------------------------
__global__ void hist_kernel(const int* __restrict__ dst, int* cnt, int E)
{
    int i = blockIdx.x * blockDim.x + threadIdx.x;
    if (i < E) atomicAdd(&cnt[dst[i]], 1);
}

__global__ void scan_kernel(const int* counts, int* rowptr, int* cursor, int N, int E)
{
    __shared__ int sm[1024];
    int tid = threadIdx.x;
    int ch  = (N + 1023) / 1024;
    int b   = tid * ch;
    int e   = min(b + ch, N);
    int s = 0;
    for (int i = b; i < e; i++) s += counts[i];
    sm[tid] = s;
    __syncthreads();
    for (int off = 1; off < 1024; off <<= 1) {
        int t = (tid >= off) ? sm[tid - off] : 0;
        __syncthreads();
        sm[tid] += t;
        __syncthreads();
    }
    int run = (tid == 0) ? 0 : sm[tid - 1];
    for (int i = b; i < e; i++) {
        int c = counts[i];
        rowptr[i] = run;
        cursor[i] = run;
        run += c;
    }
    if (tid == 0) rowptr[N] = E;
}

__global__ void fill_kernel(const int* __restrict__ src, const int* __restrict__ dst,
                            int* cursor, int* __restrict__ srcs, int E)
{
    int i = blockIdx.x * blockDim.x + threadIdx.x;
    if (i < E) {
        int p = atomicAdd(&cursor[dst[i]], 1);
        srcs[p] = src[i];
    }
}

// ---------------------------------------------------------------------------
// Per-node attention scalars
// ---------------------------------------------------------------------------
template <int NH>
__global__ void dots_kernel(const float* __restrict__ H,
                            const float* __restrict__ a_src,
                            const float* __restrict__ a_dst,
                            float* __restrict__ es, float* __restrict__ ed, int N)
{
    int gw   = (blockIdx.x * blockDim.x + threadIdx.x) >> 5;
    int lane = threadIdx.x & 31;
    if (gw >= N) return;
    const float* h = H + (size_t)gw * NH;
    float ps = 0.f, pd = 0.f;
#pragma unroll
    for (int c = lane; c < NH; c += 32) {
        float v = h[c];
        ps += v * __ldg(&a_src[c]);
        pd += v * __ldg(&a_dst[c]);
    }
#pragma unroll
    for (int o = 16; o; o >>= 1) {
        ps += __shfl_xor_sync(0xffffffffu, ps, o);
        pd += __shfl_xor_sync(0xffffffffu, pd, o);
    }
    if (lane == 0) { es[gw] = ps; ed[gw] = pd; }
}

// ---------------------------------------------------------------------------
// Fused GAT aggregation (segment softmax + weighted gather + elu).
// Writes fp32 out only if non-null; writes bf16 hi/lo split if sh non-null.
// ---------------------------------------------------------------------------
template <int NH>
__global__ void gat_agg_kernel(const float* __restrict__ H,
                               const float* __restrict__ es,
                               const float* __restrict__ ed,
                               const int* __restrict__ rowptr,
                               const int* __restrict__ srcs,
                               const int* __restrict__ perm,
                               float* __restrict__ out,
                               uint16_t* __restrict__ sh, uint16_t* __restrict__ sl,
                               int out_ld, int out_off, int N)
{
    constexpr int R4 = NH / 128;
    int gw   = (blockIdx.x * blockDim.x + threadIdx.x) >> 5;
    int lane = threadIdx.x & 31;
    if (gw >= N) return;

    int beg = rowptr[gw], end = rowptr[gw + 1];
    int dsti = perm ? __ldg(&perm[gw]) : gw;
    float edd = __ldg(&ed[dsti]);

    float m = -INFINITY;
    for (int j = beg + lane; j < end; j += 32) {
        int s  = __ldg(&srcs[j]);
        int si = perm ? __ldg(&perm[s]) : s;
        float e = __ldg(&es[si]) + edd;
        e = e > 0.f ? e : 0.2f * e;
        m = fmaxf(m, e);
    }
#pragma unroll
    for (int o = 16; o; o >>= 1) m = fmaxf(m, __shfl_xor_sync(0xffffffffu, m, o));
    if (!isfinite(m)) m = 0.f;

    float4 acc[R4];
#pragma unroll
    for (int c = 0; c < R4; c++) acc[c] = make_float4(0.f, 0.f, 0.f, 0.f);
    float sumw = 0.f;

    for (int j = beg; j < end; ++j) {
        int s  = __ldg(&srcs[j]);
        int si = perm ? __ldg(&perm[s]) : s;
        float e = __ldg(&es[si]) + edd;
        e = e > 0.f ? e : 0.2f * e;
        float w = expf(e - m);
        sumw += w;
        const float4* h4 = reinterpret_cast<const float4*>(H + (size_t)si * NH) + lane;
#pragma unroll
        for (int c = 0; c < R4; c++) {
            float4 v = __ldg(&h4[c * 32]);
            acc[c].x += w * v.x; acc[c].y += w * v.y;
            acc[c].z += w * v.z; acc[c].w += w * v.w;
        }
    }

    float inv = 1.f / (sumw + 1e-16f);
#pragma unroll
    for (int c = 0; c < R4; c++) {
        float4 v;
        v.x = acc[c].x * inv; v.y = acc[c].y * inv;
        v.z = acc[c].z * inv; v.w = acc[c].w * inv;
        v.x = v.x > 0.f ? v.x : expm1f(v.x);
        v.y = v.y > 0.f ? v.y : expm1f(v.y);
        v.z = v.z > 0.f ? v.z : expm1f(v.z);
        v.w = v.w > 0.f ? v.w : expm1f(v.w);
        size_t idx = (size_t)gw * out_ld + out_off + (size_t)(c * 32 + lane) * 4;
        if (out) *reinterpret_cast<float4*>(out + idx) = v;
        if (sh) {
            uint16_t h0, l0, h1, l1, h2, l2, h3, l3;
            bsplit(v.x, h0, l0); bsplit(v.y, h1, l1);
            bsplit(v.z, h2, l2); bsplit(v.w, h3, l3);
            uint2 hp, lp;
            hp.x = (uint32_t)h0 | ((uint32_t)h1 << 16);
            hp.y = (uint32_t)h2 | ((uint32_t)h3 << 16);
            lp.x = (uint32_t)l0 | ((uint32_t)l1 << 16);
            lp.y = (uint32_t)l2 | ((uint32_t)l3 << 16);
            *reinterpret_cast<uint2*>(sh + idx) = hp;
            *reinterpret_cast<uint2*>(sl + idx) = lp;
        }
    }
}

// ---------------------------------------------------------------------------
// summary = sigmoid(mean(h2, axis=0))
// ---------------------------------------------------------------------------
__global__ void summary_kernel(const float* __restrict__ h2, float* __restrict__ out,
                               int N, int C)
{
    int c   = blockIdx.x;
    int tid = threadIdx.x;
    float s = 0.f;
    for (int r = tid; r < N; r += blockDim.x) s += h2[(size_t)r * C + c];
    __shared__ float sm[256];
    sm[tid] = s;
    __syncthreads();
    for (int o = 128; o; o >>= 1) {
        if (tid < o) sm[tid] += sm[tid + o];
        __syncthreads();
    }
    if (tid == 0) {
        float mval = sm[0] / (float)N;
        out[c] = 1.f / (1.f + expf(-mval));
    }
}

// ---------------------------------------------------------------------------
// Host orchestration
// ---------------------------------------------------------------------------
extern "C" void kernel_launch(void* const* d_in, const int* in_sizes, int n_in,
                              void* d_out, int out_size)
{
    const float* features    = (const float*)d_in[0];
    const float* im_features = (const float*)d_in[1];
    const float* W1x     = (const float*)d_in[2];
    const float* a1x_src = (const float*)d_in[3];
    const float* a1x_dst = (const float*)d_in[4];
    const float* W1r     = (const float*)d_in[5];
    const float* a1r_src = (const float*)d_in[6];
    const float* a1r_dst = (const float*)d_in[7];
    const float* W2      = (const float*)d_in[8];
    const float* a3_src  = (const float*)d_in[9];
    const float* a3_dst  = (const float*)d_in[10];
    const int*   ei      = (const int*)d_in[11];
    const int*   perm    = (const int*)d_in[12];

    const int N   = in_sizes[12];          // 30000
    const int E   = in_sizes[11] / 2;      // 480000
    const int NH  = in_sizes[3];           // 256
    const int INX = in_sizes[0] / N;       // 3000
    const int INR = in_sizes[1] / N;       // 2048
    const int OUT = in_sizes[8] / (2 * NH);// 64

    const int* srcI = ei;
    const int* dstI = ei + E;

    float *Hx, *Hr, *T0, *T1, *scal;
    int *rp, *cnt, *sr;
    cudaGetSymbolAddress((void**)&Hx,  g_Hx);
    cudaGetSymbolAddress((void**)&Hr,  g_Hr);
    cudaGetSymbolAddress((void**)&T0,  g_T0);
    cudaGetSymbolAddress((void**)&T1,  g_T1);
    cudaGetSymbolAddress((void**)&scal,g_scal);
    cudaGetSymbolAddress((void**)&rp,  g_rowptr);
    cudaGetSymbolAddress((void**)&cnt, g_cnt);
    cudaGetSymbolAddress((void**)&sr,  g_srcs);

    uint16_t *fxh, *fxl, *frh, *frl, *w1xTh, *w1xTl, *w1rTh, *w1rTl;
    uint16_t *w1xh, *w1xl, *w1rh, *w1rl, *w2Th, *w2Tl, *w2h, *w2l;
    uint16_t *A2h, *A2l, *B2h, *B2l, *AUh, *AUl, *Ah2h, *Ah2l;
    cudaGetSymbolAddress((void**)&fxh,  g_fx_h);   cudaGetSymbolAddress((void**)&fxl,  g_fx_l);
    cudaGetSymbolAddress((void**)&frh,  g_fr_h);   cudaGetSymbolAddress((void**)&frl,  g_fr_l);
    cudaGetSymbolAddress((void**)&w1xTh,g_w1xT_h); cudaGetSymbolAddress((void**)&w1xTl,g_w1xT_l);
    cudaGetSymbolAddress((void**)&w1rTh,g_w1rT_h); cudaGetSymbolAddress((void**)&w1rTl,g_w1rT_l);
    cudaGetSymbolAddress((void**)&w1xh, g_w1x_h);  cudaGetSymbolAddress((void**)&w1xl, g_w1x_l);
    cudaGetSymbolAddress((void**)&w1rh, g_w1r_h);  cudaGetSymbolAddress((void**)&w1rl, g_w1r_l);
    cudaGetSymbolAddress((void**)&w2Th, g_w2T_h);  cudaGetSymbolAddress((void**)&w2Tl, g_w2T_l);
    cudaGetSymbolAddress((void**)&w2h,  g_w2_h);   cudaGetSymbolAddress((void**)&w2l,  g_w2_l);
    cudaGetSymbolAddress((void**)&A2h,  g_A2_h);   cudaGetSymbolAddress((void**)&A2l,  g_A2_l);
    cudaGetSymbolAddress((void**)&B2h,  g_B2_h);   cudaGetSymbolAddress((void**)&B2l,  g_B2_l);
    cudaGetSymbolAddress((void**)&AUh,  g_AU_h);   cudaGetSymbolAddress((void**)&AUl,  g_AU_l);
    cudaGetSymbolAddress((void**)&Ah2h, g_Ah2_h);  cudaGetSymbolAddress((void**)&Ah2l, g_Ah2_l);

    cudaFuncSetAttribute(mma_gemm_bf16,
                         cudaFuncAttributeMaxDynamicSharedMemorySize, GEMM_SMEM);

    float* out = (float*)d_out;
    size_t oH2   = 0;
    size_t oH4X  = oH2   + (size_t)N * OUT;
    size_t oH4R  = oH4X  + (size_t)N * INX;
    size_t oRH2  = oH4R  + (size_t)N * INR;
    size_t oRH4X = oRH2  + (size_t)N * OUT;
    size_t oRH4R = oRH4X + (size_t)N * INX;
    size_t oSUM  = oRH4R + (size_t)N * INR;

    auto gg = [](int M, int Nn) { return dim3((unsigned)((Nn + 127) / 128),
                                              (unsigned)((M + 127) / 128)); };
    auto sg = [](int R, int CP) { return (unsigned)(((size_t)R * (CP / 4) + 255) / 256); };
    const int WGRID = (N * 32 + 255) / 256;

    // --- CSR by dst ---
    cudaMemsetAsync(cnt, 0, N * sizeof(int));
    hist_kernel<<<(E + 255) / 256, 256>>>(dstI, cnt, E);
    scan_kernel<<<1, 1024>>>(cnt, rp, cnt, N, E);
    fill_kernel<<<(E + 255) / 256, 256>>>(srcI, dstI, cnt, sr, E);

    // --- Splits of inputs / weights ---
    split_rows_kernel<<<sg(N, KPX),  256>>>(features,    N, INX, KPX,  fxh, fxl);
    split_rows_kernel<<<sg(N, INR),  256>>>(im_features, N, INR, INR,  frh, frl);
    split_rows_kernel<<<sg(INX, NH), 256>>>(W1x, INX, NH, NH, w1xh, w1xl);
    split_rows_kernel<<<sg(INR, NH), 256>>>(W1r, INR, NH, NH, w1rh, w1rl);
    split_rows_kernel<<<sg(2*NH, OUT), 256>>>(W2, 2*NH, OUT, OUT, w2h, w2l);
    splitT_kernel<<<dim3((NH  + 31)/32, (KPX  + 31)/32), 256>>>(W1x, INX, NH, KPX, w1xTh, w1xTl);
    splitT_kernel<<<dim3((NH  + 31)/32, (INR  + 31)/32), 256>>>(W1r, INR, NH, INR, w1rTh, w1rTl);
    splitT_kernel<<<dim3((OUT + 31)/32, (2*NH + 31)/32), 256>>>(W2, 2*NH, OUT, 2*NH, w2Th, w2Tl);

    // --- Forward projections ---
    mma_gemm_bf16<<<gg(N, NH), 256, GEMM_SMEM>>>(N, NH, KPX, fxh, fxl, KPX,
                                                 w1xTh, w1xTl, KPX, Hx, NH, nullptr, nullptr);
    mma_gemm_bf16<<<gg(N, NH), 256, GEMM_SMEM>>>(N, NH, INR, frh, frl, INR,
                                                 w1rTh, w1rTl, INR, Hr, NH, nullptr, nullptr);

    // --- Attention scalars + encode aggregation (split fused; fp32 out unused)
    dots_kernel<256><<<WGRID, 256>>>(Hx, a1x_src, a1x_dst, scal + 0 * N, scal + 1 * N, N);
    dots_kernel<256><<<WGRID, 256>>>(Hr, a1r_src, a1r_dst, scal + 2 * N, scal + 3 * N, N);
    gat_agg_kernel<256><<<WGRID, 256>>>(Hx, scal + 0 * N, scal + 1 * N, rp, sr, nullptr, nullptr, A2h, A2l, 512, 0,   N);
    gat_agg_kernel<256><<<WGRID, 256>>>(Hr, scal + 2 * N, scal + 3 * N, rp, sr, nullptr, nullptr, A2h, A2l, 512, 256, N);
    gat_agg_kernel<256><<<WGRID, 256>>>(Hx, scal + 0 * N, scal + 1 * N, rp, sr, perm,    nullptr, B2h, B2l, 512, 0,   N);
    gat_agg_kernel<256><<<WGRID, 256>>>(Hr, scal + 2 * N, scal + 3 * N, rp, sr, perm,    nullptr, B2h, B2l, 512, 256, N);

    // --- h2 = concat @ W2  (h2 split fused into GEMM epilogue) ---
    mma_gemm_bf16<<<gg(N, OUT), 256, GEMM_SMEM>>>(N, OUT, 2*NH, A2h, A2l, 2*NH,
                                                  w2Th, w2Tl, 2*NH, out + oH2, OUT, Ah2h, Ah2l);
    summary_kernel<<<OUT, 256>>>(out + oH2, out + oSUM, N, OUT);

    // --- Decode: orig ---
    mma_gemm_bf16<<<gg(N, 2*NH), 256, GEMM_SMEM>>>(N, 2*NH, OUT, Ah2h, Ah2l, OUT,
                                                   w2h, w2l, OUT, T0, 2*NH, nullptr, nullptr);
    dots_kernel<512><<<WGRID, 256>>>(T0, a3_src, a3_dst, scal + 0 * N, scal + 1 * N, N);
    gat_agg_kernel<512><<<WGRID, 256>>>(T0, scal + 0 * N, scal + 1 * N, rp, sr, nullptr, nullptr, AUh, AUl, 512, 0, N);
    mma_gemm_bf16<<<gg(N, INX), 256, GEMM_SMEM>>>(N, INX, NH, AUh, AUl, 2*NH,
                                                  w1xh, w1xl, NH, out + oH4X, INX, nullptr, nullptr);
    mma_gemm_bf16<<<gg(N, INR), 256, GEMM_SMEM>>>(N, INR, NH, AUh + NH, AUl + NH, 2*NH,
                                                  w1rh, w1rl, NH, out + oH4R, INR, nullptr, nullptr);

    // --- rand h2 (after orig decode so Ah2 can be reused) ---
    mma_gemm_bf16<<<gg(N, OUT), 256, GEMM_SMEM>>>(N, OUT, 2*NH, B2h, B2l, 2*NH,
                                                  w2Th, w2Tl, 2*NH, out + oRH2, OUT, Ah2h, Ah2l);

    // --- Decode: rand ---
    mma_gemm_bf16<<<gg(N, 2*NH), 256, GEMM_SMEM>>>(N, 2*NH, OUT, Ah2h, Ah2l, OUT,
                                                   w2h, w2l, OUT, T1, 2*NH, nullptr, nullptr);
    dots_kernel<512><<<WGRID, 256>>>(T1, a3_src, a3_dst, scal + 2 * N, scal + 3 * N, N);
    gat_agg_kernel<512><<<WGRID, 256>>>(T1, scal + 2 * N, scal + 3 * N, rp, sr, nullptr, nullptr, AUh, AUl, 512, 0, N);
    mma_gemm_bf16<<<gg(N, INX), 256, GEMM_SMEM>>>(N, INX, NH, AUh, AUl, 2*NH,
                                                  w1xh, w1xl, NH, out + oRH4X, INX, nullptr, nullptr);
    mma_gemm_bf16<<<gg(N, INR), 256, GEMM_SMEM>>>(N, INR, NH, AUh + NH, AUl + NH, 2*NH,
                                                  w1rh, w1rl, NH, out + oRH4R, INR, nullptr, nullptr);

    (void)n_in; (void)out_size;
}

// round 11
// speedup vs baseline: 2.7416x; 1.0581x over previous
#include <cuda_runtime.h>
#include <cuda_bf16.h>
#include <math.h>
#include <stdint.h>

// ---------------------------------------------------------------------------
// stGCL: N=30000 nodes, E=480000 edges, IN_X=3000, IN_R=2048, NH=256, OUT=64.
// ---------------------------------------------------------------------------
#define N_NODES  30000
#define E_EDGES  480000
#define KPX      3008          // IN_X padded to multiple of 32

// ---- fp32 scratch ----------------------------------------------------------
__device__ float g_Hx[N_NODES * 256];
__device__ float g_Hr[N_NODES * 256];
__device__ float g_T0[N_NODES * 512];
__device__ float g_T1[N_NODES * 512];
__device__ float g_scal[N_NODES * 4];
__device__ int   g_rowptr[N_NODES + 1];
__device__ int   g_cnt[N_NODES];
__device__ int   g_srcs[E_EDGES];

// ---- bf16 split scratch (hi/lo pairs) --------------------------------------
__device__ uint16_t g_fx_h[N_NODES * KPX],  g_fx_l[N_NODES * KPX];
__device__ uint16_t g_fr_h[N_NODES * 2048], g_fr_l[N_NODES * 2048];
__device__ uint16_t g_w1xT_h[256 * KPX],    g_w1xT_l[256 * KPX];
__device__ uint16_t g_w1rT_h[256 * 2048],   g_w1rT_l[256 * 2048];
__device__ uint16_t g_w1x_h[3000 * 256],    g_w1x_l[3000 * 256];
__device__ uint16_t g_w1r_h[2048 * 256],    g_w1r_l[2048 * 256];
__device__ uint16_t g_w2T_h[64 * 512],      g_w2T_l[64 * 512];
__device__ uint16_t g_w2_h[512 * 64],       g_w2_l[512 * 64];
__device__ uint16_t g_A2_h[N_NODES * 512],  g_A2_l[N_NODES * 512];   // concat(T0) split
__device__ uint16_t g_B2_h[N_NODES * 512],  g_B2_l[N_NODES * 512];   // concat(T1) split
__device__ uint16_t g_AU_h[N_NODES * 512],  g_AU_l[N_NODES * 512];   // h3 split
__device__ uint16_t g_Ah2_h[N_NODES * 64],  g_Ah2_l[N_NODES * 64];   // h2 split

// ---------------------------------------------------------------------------
// bf16 split: x = hi + lo (both bf16); kept products hh+lh+hl
// ---------------------------------------------------------------------------
__device__ __forceinline__ void bsplit(float x, uint16_t& h, uint16_t& l)
{
    __nv_bfloat16 hb = __float2bfloat16_rn(x);
    float hf = __bfloat162float(hb);
    __nv_bfloat16 lb = __float2bfloat16_rn(x - hf);
    h = __bfloat16_as_ushort(hb);
    l = __bfloat16_as_ushort(lb);
}

// mma m16n8k16 bf16, fp32 accum
#define MMA_BF16(d, a, b)                                                     \
    asm volatile(                                                             \
        "mma.sync.aligned.m16n8k16.row.col.f32.bf16.bf16.f32 "                \
        "{%0,%1,%2,%3},{%4,%5,%6,%7},{%8,%9},{%0,%1,%2,%3};"                  \
        : "+f"((d)[0]), "+f"((d)[1]), "+f"((d)[2]), "+f"((d)[3])              \
        : "r"((a)[0]), "r"((a)[1]), "r"((a)[2]), "r"((a)[3]),                 \
          "r"((b)[0]), "r"((b)[1]))

// ldmatrix x4 (non-transposed)
#define LDSM4(r0, r1, r2, r3, addr)                                           \
    asm volatile("ldmatrix.sync.aligned.m8n8.x4.shared.b16 {%0,%1,%2,%3}, [%4];" \
        : "=r"(r0), "=r"(r1), "=r"(r2), "=r"(r3) : "r"(addr))

#define WSTR   20                 // words per smem row (16 data + 4 pad)
#define TILE_W (128 * WSTR)       // words per 128x32 bf16 tile
#define STG    (4 * TILE_W)       // words per pipeline stage (Ah,Al,Bh,Bl)
#define GEMM_SMEM (2 * STG * 4)   // bytes

// 16B cp.async of one chunk; 2 chunks/thread per tile
__device__ __forceinline__ void copy_tile_async(
    uint32_t s_byte_base, const uint16_t* __restrict__ g, int ld,
    int row0, int rowmax, int k0, int tid)
{
#pragma unroll
    for (int i = 0; i < 2; i++) {
        int ch  = tid * 2 + i;          // 0..511
        int row = ch >> 2;              // 0..127
        int c   = ch & 3;               // 16B chunk within 64B row
        int gr  = row0 + row;
        if (gr > rowmax) gr = rowmax;
        const uint16_t* src = g + (size_t)gr * ld + k0 + c * 8;
        uint32_t dst = s_byte_base + (uint32_t)(row * WSTR + c * 4) * 4u;
        asm volatile("cp.async.cg.shared.global [%0], [%1], 16;"
                     :: "r"(dst), "l"(src) : "memory");
    }
}

// ---------------------------------------------------------------------------
// bf16x3 GEMM, both operands pre-split bf16, K-major:
//   C[M,N] = (Ahi+Alo)[M,K] * (Bhi+Blo)[N,K]^T   (keeping hh+lh+hl)
// 128x128 block, BK=32, 256 threads, double-buffered cp.async pipeline.
// Fragment loads via ldmatrix.x4 (12 LDSM per k16-step vs 96 scalar LDS).
// Optional fused bf16-split of C into (Chi, Clo).
// Requires: K % 32 == 0, lda/ldb % 8 == 0.
// ---------------------------------------------------------------------------
__global__ __launch_bounds__(256, 2)
void mma_gemm_bf16(int M, int N, int K,
                   const uint16_t* __restrict__ Ahi, const uint16_t* __restrict__ Alo, int lda,
                   const uint16_t* __restrict__ Bhi, const uint16_t* __restrict__ Blo, int ldb,
                   float* __restrict__ C, int ldc,
                   uint16_t* __restrict__ Chi, uint16_t* __restrict__ Clo)
{
    extern __shared__ uint32_t smem[];
    const uint32_t sb = (uint32_t)__cvta_generic_to_shared(smem);

    const int tid  = threadIdx.x;
    const int lane = tid & 31;
    const int wid  = tid >> 5;
    const int g    = lane >> 2;
    const int tig  = lane & 3;
    const int wm   = (wid & 1) * 64;
    const int wn   = (wid >> 1) * 32;
    const int m0   = blockIdx.y * 128;
    const int n0   = blockIdx.x * 128;
    const int nk   = K >> 5;

    // ldmatrix per-lane address bases (byte offsets within a tile)
    const int lr = lane & 7;       // row within 8x8 matrix
    const int lq = lane >> 3;      // matrix index 0..3
    // A matrices: q&1 -> +8 m-rows, q>>1 -> +16B (k8..15)
    const uint32_t aBase = (uint32_t)(((wm + (lq & 1) * 8 + lr) * WSTR + (lq >> 1) * 4) * 4);
    // B matrices: q>>1 -> +8 n-rows (next nf), q&1 -> +16B (k8..15)
    const uint32_t bBase = (uint32_t)(((wn + (lq >> 1) * 8 + lr) * WSTR + (lq & 1) * 4) * 4);

    float acc[4][4][4];
#pragma unroll
    for (int i = 0; i < 4; i++)
#pragma unroll
        for (int j = 0; j < 4; j++)
#pragma unroll
            for (int c = 0; c < 4; c++) acc[i][j][c] = 0.f;

    auto load = [&](int s, int kt) {
        int k0 = kt << 5;
        uint32_t base = sb + (uint32_t)(s * STG) * 4u;
        copy_tile_async(base,                  Ahi, lda, m0, M - 1, k0, tid);
        copy_tile_async(base + TILE_W * 4,     Alo, lda, m0, M - 1, k0, tid);
        copy_tile_async(base + 2 * TILE_W * 4, Bhi, ldb, n0, N - 1, k0, tid);
        copy_tile_async(base + 3 * TILE_W * 4, Blo, ldb, n0, N - 1, k0, tid);
    };

    load(0, 0);
    asm volatile("cp.async.commit_group;" ::: "memory");

    int cur = 0;
    for (int kt = 0; kt < nk; kt++) {
        if (kt + 1 < nk) load(cur ^ 1, kt + 1);
        asm volatile("cp.async.commit_group;" ::: "memory");
        asm volatile("cp.async.wait_group 1;" ::: "memory");
        __syncthreads();

        const uint32_t sA = sb + (uint32_t)(cur * STG) * 4u;
        const uint32_t sB = sA + 2 * TILE_W * 4;

#pragma unroll
        for (int ws = 0; ws < 16; ws += 8) {     // two k16 steps per BK=32
            uint32_t ah[4][4], al[4][4];
#pragma unroll
            for (int mf = 0; mf < 4; mf++) {
                uint32_t addr = sA + aBase + (uint32_t)((mf * 16 * WSTR + ws) * 4);
                LDSM4(ah[mf][0], ah[mf][1], ah[mf][2], ah[mf][3], addr);
                LDSM4(al[mf][0], al[mf][1], al[mf][2], al[mf][3], addr + TILE_W * 4);
            }
            uint32_t bh[4][2], bl[4][2];
#pragma unroll
            for (int nfp = 0; nfp < 2; nfp++) {
                uint32_t addr = sB + bBase + (uint32_t)((nfp * 16 * WSTR + ws) * 4);
                LDSM4(bh[2 * nfp][0], bh[2 * nfp][1],
                      bh[2 * nfp + 1][0], bh[2 * nfp + 1][1], addr);
                LDSM4(bl[2 * nfp][0], bl[2 * nfp][1],
                      bl[2 * nfp + 1][0], bl[2 * nfp + 1][1], addr + TILE_W * 4);
            }
#pragma unroll
            for (int mf = 0; mf < 4; mf++)
#pragma unroll
                for (int nf = 0; nf < 4; nf++)
                    MMA_BF16(acc[mf][nf], ah[mf], bh[nf]);
#pragma unroll
            for (int mf = 0; mf < 4; mf++)
#pragma unroll
                for (int nf = 0; nf < 4; nf++)
                    MMA_BF16(acc[mf][nf], al[mf], bh[nf]);
#pragma unroll
            for (int mf = 0; mf < 4; mf++)
#pragma unroll
                for (int nf = 0; nf < 4; nf++)
                    MMA_BF16(acc[mf][nf], ah[mf], bl[nf]);
        }
        __syncthreads();
        cur ^= 1;
    }

    // ---- Epilogue (optionally also write bf16 hi/lo split of C)
#pragma unroll
    for (int mf = 0; mf < 4; mf++) {
        int gm1 = m0 + wm + mf * 16 + g;
        int gm2 = gm1 + 8;
#pragma unroll
        for (int nf = 0; nf < 4; nf++) {
            int gn = n0 + wn + nf * 8 + tig * 2;
#pragma unroll
            for (int half = 0; half < 2; half++) {
                int gm = half ? gm2 : gm1;
                if (gm >= M) continue;
                float v0 = acc[mf][nf][half * 2];
                float v1 = acc[mf][nf][half * 2 + 1];
                if (gn < N) {
                    size_t idx = (size_t)gm * ldc + gn;
                    C[idx] = v0;
                    if (Chi) { uint16_t h, l; bsplit(v0, h, l); Chi[idx] = h; Clo[idx] = l; }
                }
                if (gn + 1 < N) {
                    size_t idx = (size_t)gm * ldc + gn + 1;
                    C[idx] = v1;
                    if (Chi) { uint16_t h, l; bsplit(v1, h, l); Chi[idx] = h; Clo[idx] = l; }
                }
            }
        }
    }
}

// ---------------------------------------------------------------------------
// Split kernels (inputs/weights only)
// ---------------------------------------------------------------------------
__global__ void split_rows_kernel(const float* __restrict__ in, int R, int C, int CP,
                                  uint16_t* __restrict__ hi, uint16_t* __restrict__ lo)
{
    int perRow = CP >> 2;
    int t = blockIdx.x * blockDim.x + threadIdx.x;
    if (t >= R * perRow) return;
    int row = t / perRow;
    int c   = (t - row * perRow) << 2;
    float4 v = make_float4(0.f, 0.f, 0.f, 0.f);
    if (c < C) v = *reinterpret_cast<const float4*>(in + (size_t)row * C + c);
    uint16_t h[4], l[4];
    bsplit(v.x, h[0], l[0]);
    bsplit(v.y, h[1], l[1]);
    bsplit(v.z, h[2], l[2]);
    bsplit(v.w, h[3], l[3]);
    uint2 hp, lp;
    hp.x = (uint32_t)h[0] | ((uint32_t)h[1] << 16);
    hp.y = (uint32_t)h[2] | ((uint32_t)h[3] << 16);
    lp.x = (uint32_t)l[0] | ((uint32_t)l[1] << 16);
    lp.y = (uint32_t)l[2] | ((uint32_t)l[3] << 16);
    *reinterpret_cast<uint2*>(hi + (size_t)row * CP + c) = hp;
    *reinterpret_cast<uint2*>(lo + (size_t)row * CP + c) = lp;
}

__global__ void splitT_kernel(const float* __restrict__ in, int R, int C, int RP,
                              uint16_t* __restrict__ hi, uint16_t* __restrict__ lo)
{
    __shared__ float tile[32][33];
    int tx = threadIdx.x & 31;
    int ty = threadIdx.x >> 5;
    int r0 = blockIdx.y * 32;
    int c0 = blockIdx.x * 32;
#pragma unroll
    for (int j = ty; j < 32; j += 8) {
        int r = r0 + j, c = c0 + tx;
        tile[j][tx] = (r < R && c < C) ? in[(size_t)r * C + c] : 0.f;
    }
    __syncthreads();
#pragma unroll
    for (int j = ty; j < 32; j += 8) {
        int oc  = c0 + j;
        int orr = r0 + tx;
        if (oc < C && orr < RP) {
            uint16_t h, l;
            bsplit(tile[tx][j], h, l);
            hi[(size_t)oc * RP + orr] = h;
            lo[(size_t)oc * RP + orr] = l;
        }
    }
}

// ---------------------------------------------------------------------------
// CSR build
// ---------------------------------------------------------------------------
__global__ void hist_kernel(const int* __restrict__ dst, int* cnt, int E)
{
    int i = blockIdx.x * blockDim.x + threadIdx.x;
    if (i < E) atomicAdd(&cnt[dst[i]], 1);
}

__global__ void scan_kernel(const int* counts, int* rowptr, int* cursor, int N, int E)
{
    __shared__ int sm[1024];
    int tid = threadIdx.x;
    int ch  = (N + 1023) / 1024;
    int b   = tid * ch;
    int e   = min(b + ch, N);
    int s = 0;
    for (int i = b; i < e; i++) s += counts[i];
    sm[tid] = s;
    __syncthreads();
    for (int off = 1; off < 1024; off <<= 1) {
        int t = (tid >= off) ? sm[tid - off] : 0;
        __syncthreads();
        sm[tid] += t;
        __syncthreads();
    }
    int run = (tid == 0) ? 0 : sm[tid - 1];
    for (int i = b; i < e; i++) {
        int c = counts[i];
        rowptr[i] = run;
        cursor[i] = run;
        run += c;
    }
    if (tid == 0) rowptr[N] = E;
}

__global__ void fill_kernel(const int* __restrict__ src, const int* __restrict__ dst,
                            int* cursor, int* __restrict__ srcs, int E)
{
    int i = blockIdx.x * blockDim.x + threadIdx.x;
    if (i < E) {
        int p = atomicAdd(&cursor[dst[i]], 1);
        srcs[p] = src[i];
    }
}

// ---------------------------------------------------------------------------
// Per-node attention scalars
// ---------------------------------------------------------------------------
template <int NH>
__global__ void dots_kernel(const float* __restrict__ H,
                            const float* __restrict__ a_src,
                            const float* __restrict__ a_dst,
                            float* __restrict__ es, float* __restrict__ ed, int N)
{
    int gw   = (blockIdx.x * blockDim.x + threadIdx.x) >> 5;
    int lane = threadIdx.x & 31;
    if (gw >= N) return;
    const float* h = H + (size_t)gw * NH;
    float ps = 0.f, pd = 0.f;
#pragma unroll
    for (int c = lane; c < NH; c += 32) {
        float v = h[c];
        ps += v * __ldg(&a_src[c]);
        pd += v * __ldg(&a_dst[c]);
    }
#pragma unroll
    for (int o = 16; o; o >>= 1) {
        ps += __shfl_xor_sync(0xffffffffu, ps, o);
        pd += __shfl_xor_sync(0xffffffffu, pd, o);
    }
    if (lane == 0) { es[gw] = ps; ed[gw] = pd; }
}

// ---------------------------------------------------------------------------
// Fused GAT aggregation (segment softmax + weighted gather + elu).
// Writes fp32 out only if non-null; writes bf16 hi/lo split if sh non-null.
// ---------------------------------------------------------------------------
template <int NH>
__global__ void gat_agg_kernel(const float* __restrict__ H,
                               const float* __restrict__ es,
                               const float* __restrict__ ed,
                               const int* __restrict__ rowptr,
                               const int* __restrict__ srcs,
                               const int* __restrict__ perm,
                               float* __restrict__ out,
                               uint16_t* __restrict__ sh, uint16_t* __restrict__ sl,
                               int out_ld, int out_off, int N)
{
    constexpr int R4 = NH / 128;
    int gw   = (blockIdx.x * blockDim.x + threadIdx.x) >> 5;
    int lane = threadIdx.x & 31;
    if (gw >= N) return;

    int beg = rowptr[gw], end = rowptr[gw + 1];
    int dsti = perm ? __ldg(&perm[gw]) : gw;
    float edd = __ldg(&ed[dsti]);

    float m = -INFINITY;
    for (int j = beg + lane; j < end; j += 32) {
        int s  = __ldg(&srcs[j]);
        int si = perm ? __ldg(&perm[s]) : s;
        float e = __ldg(&es[si]) + edd;
        e = e > 0.f ? e : 0.2f * e;
        m = fmaxf(m, e);
    }
#pragma unroll
    for (int o = 16; o; o >>= 1) m = fmaxf(m, __shfl_xor_sync(0xffffffffu, m, o));
    if (!isfinite(m)) m = 0.f;

    float4 acc[R4];
#pragma unroll
    for (int c = 0; c < R4; c++) acc[c] = make_float4(0.f, 0.f, 0.f, 0.f);
    float sumw = 0.f;

    for (int j = beg; j < end; ++j) {
        int s  = __ldg(&srcs[j]);
        int si = perm ? __ldg(&perm[s]) : s;
        float e = __ldg(&es[si]) + edd;
        e = e > 0.f ? e : 0.2f * e;
        float w = expf(e - m);
        sumw += w;
        const float4* h4 = reinterpret_cast<const float4*>(H + (size_t)si * NH) + lane;
#pragma unroll
        for (int c = 0; c < R4; c++) {
            float4 v = __ldg(&h4[c * 32]);
            acc[c].x += w * v.x; acc[c].y += w * v.y;
            acc[c].z += w * v.z; acc[c].w += w * v.w;
        }
    }

    float inv = 1.f / (sumw + 1e-16f);
#pragma unroll
    for (int c = 0; c < R4; c++) {
        float4 v;
        v.x = acc[c].x * inv; v.y = acc[c].y * inv;
        v.z = acc[c].z * inv; v.w = acc[c].w * inv;
        v.x = v.x > 0.f ? v.x : expm1f(v.x);
        v.y = v.y > 0.f ? v.y : expm1f(v.y);
        v.z = v.z > 0.f ? v.z : expm1f(v.z);
        v.w = v.w > 0.f ? v.w : expm1f(v.w);
        size_t idx = (size_t)gw * out_ld + out_off + (size_t)(c * 32 + lane) * 4;
        if (out) *reinterpret_cast<float4*>(out + idx) = v;
        if (sh) {
            uint16_t h0, l0, h1, l1, h2, l2, h3, l3;
            bsplit(v.x, h0, l0); bsplit(v.y, h1, l1);
            bsplit(v.z, h2, l2); bsplit(v.w, h3, l3);
            uint2 hp, lp;
            hp.x = (uint32_t)h0 | ((uint32_t)h1 << 16);
            hp.y = (uint32_t)h2 | ((uint32_t)h3 << 16);
            lp.x = (uint32_t)l0 | ((uint32_t)l1 << 16);
            lp.y = (uint32_t)l2 | ((uint32_t)l3 << 16);
            *reinterpret_cast<uint2*>(sh + idx) = hp;
            *reinterpret_cast<uint2*>(sl + idx) = lp;
        }
    }
}

// ---------------------------------------------------------------------------
// summary = sigmoid(mean(h2, axis=0))
// ---------------------------------------------------------------------------
__global__ void summary_kernel(const float* __restrict__ h2, float* __restrict__ out,
                               int N, int C)
{
    int c   = blockIdx.x;
    int tid = threadIdx.x;
    float s = 0.f;
    for (int r = tid; r < N; r += blockDim.x) s += h2[(size_t)r * C + c];
    __shared__ float sm[256];
    sm[tid] = s;
    __syncthreads();
    for (int o = 128; o; o >>= 1) {
        if (tid < o) sm[tid] += sm[tid + o];
        __syncthreads();
    }
    if (tid == 0) {
        float mval = sm[0] / (float)N;
        out[c] = 1.f / (1.f + expf(-mval));
    }
}

// ---------------------------------------------------------------------------
// Host orchestration
// ---------------------------------------------------------------------------
extern "C" void kernel_launch(void* const* d_in, const int* in_sizes, int n_in,
                              void* d_out, int out_size)
{
    const float* features    = (const float*)d_in[0];
    const float* im_features = (const float*)d_in[1];
    const float* W1x     = (const float*)d_in[2];
    const float* a1x_src = (const float*)d_in[3];
    const float* a1x_dst = (const float*)d_in[4];
    const float* W1r     = (const float*)d_in[5];
    const float* a1r_src = (const float*)d_in[6];
    const float* a1r_dst = (const float*)d_in[7];
    const float* W2      = (const float*)d_in[8];
    const float* a3_src  = (const float*)d_in[9];
    const float* a3_dst  = (const float*)d_in[10];
    const int*   ei      = (const int*)d_in[11];
    const int*   perm    = (const int*)d_in[12];

    const int N   = in_sizes[12];          // 30000
    const int E   = in_sizes[11] / 2;      // 480000
    const int NH  = in_sizes[3];           // 256
    const int INX = in_sizes[0] / N;       // 3000
    const int INR = in_sizes[1] / N;       // 2048
    const int OUT = in_sizes[8] / (2 * NH);// 64

    const int* srcI = ei;
    const int* dstI = ei + E;

    float *Hx, *Hr, *T0, *T1, *scal;
    int *rp, *cnt, *sr;
    cudaGetSymbolAddress((void**)&Hx,  g_Hx);
    cudaGetSymbolAddress((void**)&Hr,  g_Hr);
    cudaGetSymbolAddress((void**)&T0,  g_T0);
    cudaGetSymbolAddress((void**)&T1,  g_T1);
    cudaGetSymbolAddress((void**)&scal,g_scal);
    cudaGetSymbolAddress((void**)&rp,  g_rowptr);
    cudaGetSymbolAddress((void**)&cnt, g_cnt);
    cudaGetSymbolAddress((void**)&sr,  g_srcs);

    uint16_t *fxh, *fxl, *frh, *frl, *w1xTh, *w1xTl, *w1rTh, *w1rTl;
    uint16_t *w1xh, *w1xl, *w1rh, *w1rl, *w2Th, *w2Tl, *w2h, *w2l;
    uint16_t *A2h, *A2l, *B2h, *B2l, *AUh, *AUl, *Ah2h, *Ah2l;
    cudaGetSymbolAddress((void**)&fxh,  g_fx_h);   cudaGetSymbolAddress((void**)&fxl,  g_fx_l);
    cudaGetSymbolAddress((void**)&frh,  g_fr_h);   cudaGetSymbolAddress((void**)&frl,  g_fr_l);
    cudaGetSymbolAddress((void**)&w1xTh,g_w1xT_h); cudaGetSymbolAddress((void**)&w1xTl,g_w1xT_l);
    cudaGetSymbolAddress((void**)&w1rTh,g_w1rT_h); cudaGetSymbolAddress((void**)&w1rTl,g_w1rT_l);
    cudaGetSymbolAddress((void**)&w1xh, g_w1x_h);  cudaGetSymbolAddress((void**)&w1xl, g_w1x_l);
    cudaGetSymbolAddress((void**)&w1rh, g_w1r_h);  cudaGetSymbolAddress((void**)&w1rl, g_w1r_l);
    cudaGetSymbolAddress((void**)&w2Th, g_w2T_h);  cudaGetSymbolAddress((void**)&w2Tl, g_w2T_l);
    cudaGetSymbolAddress((void**)&w2h,  g_w2_h);   cudaGetSymbolAddress((void**)&w2l,  g_w2_l);
    cudaGetSymbolAddress((void**)&A2h,  g_A2_h);   cudaGetSymbolAddress((void**)&A2l,  g_A2_l);
    cudaGetSymbolAddress((void**)&B2h,  g_B2_h);   cudaGetSymbolAddress((void**)&B2l,  g_B2_l);
    cudaGetSymbolAddress((void**)&AUh,  g_AU_h);   cudaGetSymbolAddress((void**)&AUl,  g_AU_l);
    cudaGetSymbolAddress((void**)&Ah2h, g_Ah2_h);  cudaGetSymbolAddress((void**)&Ah2l, g_Ah2_l);

    cudaFuncSetAttribute(mma_gemm_bf16,
                         cudaFuncAttributeMaxDynamicSharedMemorySize, GEMM_SMEM);

    float* out = (float*)d_out;
    size_t oH2   = 0;
    size_t oH4X  = oH2   + (size_t)N * OUT;
    size_t oH4R  = oH4X  + (size_t)N * INX;
    size_t oRH2  = oH4R  + (size_t)N * INR;
    size_t oRH4X = oRH2  + (size_t)N * OUT;
    size_t oRH4R = oRH4X + (size_t)N * INX;
    size_t oSUM  = oRH4R + (size_t)N * INR;

    auto gg = [](int M, int Nn) { return dim3((unsigned)((Nn + 127) / 128),
                                              (unsigned)((M + 127) / 128)); };
    auto sg = [](int R, int CP) { return (unsigned)(((size_t)R * (CP / 4) + 255) / 256); };
    const int WGRID = (N * 32 + 255) / 256;

    // --- CSR by dst ---
    cudaMemsetAsync(cnt, 0, N * sizeof(int));
    hist_kernel<<<(E + 255) / 256, 256>>>(dstI, cnt, E);
    scan_kernel<<<1, 1024>>>(cnt, rp, cnt, N, E);
    fill_kernel<<<(E + 255) / 256, 256>>>(srcI, dstI, cnt, sr, E);

    // --- Splits of inputs / weights ---
    split_rows_kernel<<<sg(N, KPX),  256>>>(features,    N, INX, KPX,  fxh, fxl);
    split_rows_kernel<<<sg(N, INR),  256>>>(im_features, N, INR, INR,  frh, frl);
    split_rows_kernel<<<sg(INX, NH), 256>>>(W1x, INX, NH, NH, w1xh, w1xl);
    split_rows_kernel<<<sg(INR, NH), 256>>>(W1r, INR, NH, NH, w1rh, w1rl);
    split_rows_kernel<<<sg(2*NH, OUT), 256>>>(W2, 2*NH, OUT, OUT, w2h, w2l);
    splitT_kernel<<<dim3((NH  + 31)/32, (KPX  + 31)/32), 256>>>(W1x, INX, NH, KPX, w1xTh, w1xTl);
    splitT_kernel<<<dim3((NH  + 31)/32, (INR  + 31)/32), 256>>>(W1r, INR, NH, INR, w1rTh, w1rTl);
    splitT_kernel<<<dim3((OUT + 31)/32, (2*NH + 31)/32), 256>>>(W2, 2*NH, OUT, 2*NH, w2Th, w2Tl);

    // --- Forward projections ---
    mma_gemm_bf16<<<gg(N, NH), 256, GEMM_SMEM>>>(N, NH, KPX, fxh, fxl, KPX,
                                                 w1xTh, w1xTl, KPX, Hx, NH, nullptr, nullptr);
    mma_gemm_bf16<<<gg(N, NH), 256, GEMM_SMEM>>>(N, NH, INR, frh, frl, INR,
                                                 w1rTh, w1rTl, INR, Hr, NH, nullptr, nullptr);

    // --- Attention scalars + encode aggregation (split fused; fp32 out unused)
    dots_kernel<256><<<WGRID, 256>>>(Hx, a1x_src, a1x_dst, scal + 0 * N, scal + 1 * N, N);
    dots_kernel<256><<<WGRID, 256>>>(Hr, a1r_src, a1r_dst, scal + 2 * N, scal + 3 * N, N);
    gat_agg_kernel<256><<<WGRID, 256>>>(Hx, scal + 0 * N, scal + 1 * N, rp, sr, nullptr, nullptr, A2h, A2l, 512, 0,   N);
    gat_agg_kernel<256><<<WGRID, 256>>>(Hr, scal + 2 * N, scal + 3 * N, rp, sr, nullptr, nullptr, A2h, A2l, 512, 256, N);
    gat_agg_kernel<256><<<WGRID, 256>>>(Hx, scal + 0 * N, scal + 1 * N, rp, sr, perm,    nullptr, B2h, B2l, 512, 0,   N);
    gat_agg_kernel<256><<<WGRID, 256>>>(Hr, scal + 2 * N, scal + 3 * N, rp, sr, perm,    nullptr, B2h, B2l, 512, 256, N);

    // --- h2 = concat @ W2  (h2 split fused into GEMM epilogue) ---
    mma_gemm_bf16<<<gg(N, OUT), 256, GEMM_SMEM>>>(N, OUT, 2*NH, A2h, A2l, 2*NH,
                                                  w2Th, w2Tl, 2*NH, out + oH2, OUT, Ah2h, Ah2l);
    summary_kernel<<<OUT, 256>>>(out + oH2, out + oSUM, N, OUT);

    // --- Decode: orig ---
    mma_gemm_bf16<<<gg(N, 2*NH), 256, GEMM_SMEM>>>(N, 2*NH, OUT, Ah2h, Ah2l, OUT,
                                                   w2h, w2l, OUT, T0, 2*NH, nullptr, nullptr);
    dots_kernel<512><<<WGRID, 256>>>(T0, a3_src, a3_dst, scal + 0 * N, scal + 1 * N, N);
    gat_agg_kernel<512><<<WGRID, 256>>>(T0, scal + 0 * N, scal + 1 * N, rp, sr, nullptr, nullptr, AUh, AUl, 512, 0, N);
    mma_gemm_bf16<<<gg(N, INX), 256, GEMM_SMEM>>>(N, INX, NH, AUh, AUl, 2*NH,
                                                  w1xh, w1xl, NH, out + oH4X, INX, nullptr, nullptr);
    mma_gemm_bf16<<<gg(N, INR), 256, GEMM_SMEM>>>(N, INR, NH, AUh + NH, AUl + NH, 2*NH,
                                                  w1rh, w1rl, NH, out + oH4R, INR, nullptr, nullptr);

    // --- rand h2 (after orig decode so Ah2 can be reused) ---
    mma_gemm_bf16<<<gg(N, OUT), 256, GEMM_SMEM>>>(N, OUT, 2*NH, B2h, B2l, 2*NH,
                                                  w2Th, w2Tl, 2*NH, out + oRH2, OUT, Ah2h, Ah2l);

    // --- Decode: rand ---
    mma_gemm_bf16<<<gg(N, 2*NH), 256, GEMM_SMEM>>>(N, 2*NH, OUT, Ah2h, Ah2l, OUT,
                                                   w2h, w2l, OUT, T1, 2*NH, nullptr, nullptr);
    dots_kernel<512><<<WGRID, 256>>>(T1, a3_src, a3_dst, scal + 2 * N, scal + 3 * N, N);
    gat_agg_kernel<512><<<WGRID, 256>>>(T1, scal + 2 * N, scal + 3 * N, rp, sr, nullptr, nullptr, AUh, AUl, 512, 0, N);
    mma_gemm_bf16<<<gg(N, INX), 256, GEMM_SMEM>>>(N, INX, NH, AUh, AUl, 2*NH,
                                                  w1xh, w1xl, NH, out + oRH4X, INX, nullptr, nullptr);
    mma_gemm_bf16<<<gg(N, INR), 256, GEMM_SMEM>>>(N, INR, NH, AUh + NH, AUl + NH, 2*NH,
                                                  w1rh, w1rl, NH, out + oRH4R, INR, nullptr, nullptr);

    (void)n_in; (void)out_size;
}